// round 1
// baseline (speedup 1.0000x reference)
#include <cuda_runtime.h>

#define NNODES 50000
#define NEDGES 800000
#define ND     64      // node feature dim
#define H      128     // hidden
#define OUTD   64      // output dim
#define BN_EPS 1e-5f

// ---------------- scratch (device globals: no allocations allowed) ----------
__device__ float g_h1[(long long)NEDGES * H];   // edge hidden pre-BN   (409.6 MB)
__device__ float g_agg[NNODES * H];             // scatter-add target   (25.6 MB)
__device__ float g_h2[NNODES * H];              // node hidden pre-BN   (25.6 MB)
__device__ float g_sum[H];
__device__ float g_sumsq[H];
__device__ float g_scale[H];
__device__ float g_shift[H];

// ---------------- f32x2 packed-FMA helpers (Blackwell FFMA2) ----------------
__device__ __forceinline__ unsigned long long pack2(float a, float b) {
    unsigned long long r;
    asm("mov.b64 %0, {%1, %2};" : "=l"(r) : "f"(a), "f"(b));
    return r;
}
__device__ __forceinline__ void fma2(unsigned long long& d, unsigned long long a,
                                     unsigned long long b) {
    asm("fma.rn.f32x2 %0, %1, %2, %0;" : "+l"(d) : "l"(a), "l"(b));
}
__device__ __forceinline__ float2 unpack2(unsigned long long v) {
    float2 f;
    asm("mov.b64 {%0, %1}, %2;" : "=f"(f.x), "=f"(f.y) : "l"(v));
    return f;
}

// ---------------- kernel 0: zero accumulators -------------------------------
__global__ void zero_kernel() {
    int i = blockIdx.x * blockDim.x + threadIdx.x;
    const float4 z = {0.f, 0.f, 0.f, 0.f};
    if (i < NNODES * H / 4) ((float4*)g_agg)[i] = z;
    if (i < H / 4) {
        ((float4*)g_sum)[i] = z;
        ((float4*)g_sumsq)[i] = z;
    }
}

// ---------------- BN finalize: scale/shift from sums; re-zero sums ----------
__global__ void finalize_bn(const float* __restrict__ gamma,
                            const float* __restrict__ beta, float invM) {
    int c = threadIdx.x;  // 128 threads
    float mean = g_sum[c] * invM;
    float var  = g_sumsq[c] * invM - mean * mean;
    float sc   = gamma[c] * rsqrtf(var + BN_EPS);
    g_scale[c] = sc;
    g_shift[c] = beta[c] - mean * sc;
    g_sum[c] = 0.f;
    g_sumsq[c] = 0.f;
}

// ============================================================================
// Edge GEMM1: h1[e] = concat(x[row[e]], edge_attr[e]) @ W1a + b1a
// tile: 64 rows x 128 cols, 256 threads, thread microtile 4x8 (4 f32x2 pairs)
// fused: per-column sum / sumsq accumulation (block-reduce + atomics)
// ============================================================================
__global__ __launch_bounds__(256) void edge_gemm1(
    const float* __restrict__ x, const int* __restrict__ ei,
    const float* __restrict__ ea, const float* __restrict__ W,
    const float* __restrict__ bias) {
    __shared__ float As[16][64];
    __shared__ float Ws[16][128];
    __shared__ float red[16][128];
    __shared__ int rowidx[64];

    const int tid = threadIdx.x;
    const int tx = tid & 15;   // col group: cols tx*8 .. tx*8+7
    const int ty = tid >> 4;   // row group: rows ty*4 .. ty*4+3
    const int row0 = blockIdx.x * 64;

    if (tid < 64) rowidx[tid] = ei[row0 + tid];  // source node per edge
    __syncthreads();

    unsigned long long acc[4][4];
#pragma unroll
    for (int i = 0; i < 4; i++)
#pragma unroll
        for (int j = 0; j < 4; j++) acc[i][j] = 0ULL;

    const int lr  = tid & 63;         // A-load local row
    const int lk4 = (tid >> 6) << 2;  // A-load k offset {0,4,8,12}

    for (int k0 = 0; k0 < 128; k0 += 16) {
        int kk = k0 + lk4;
        float4 v;
        if (kk < 64)
            v = *(const float4*)&x[rowidx[lr] * ND + kk];
        else
            v = *(const float4*)&ea[(row0 + lr) * ND + (kk - 64)];
        As[lk4 + 0][lr] = v.x; As[lk4 + 1][lr] = v.y;
        As[lk4 + 2][lr] = v.z; As[lk4 + 3][lr] = v.w;

        int idx = tid * 8;
        int wkr = idx >> 7, wc = idx & 127;
        *(float4*)&Ws[wkr][wc]     = *(const float4*)&W[(k0 + wkr) * H + wc];
        *(float4*)&Ws[wkr][wc + 4] = *(const float4*)&W[(k0 + wkr) * H + wc + 4];
        __syncthreads();

#pragma unroll
        for (int k = 0; k < 16; k++) {
            float4 a4 = *(const float4*)&As[k][ty * 4];
            float4 b0 = *(const float4*)&Ws[k][tx * 8];
            float4 b1 = *(const float4*)&Ws[k][tx * 8 + 4];
            unsigned long long bp[4] = {pack2(b0.x, b0.y), pack2(b0.z, b0.w),
                                        pack2(b1.x, b1.y), pack2(b1.z, b1.w)};
            float ar[4] = {a4.x, a4.y, a4.z, a4.w};
#pragma unroll
            for (int i = 0; i < 4; i++) {
                unsigned long long ap = pack2(ar[i], ar[i]);
#pragma unroll
                for (int j = 0; j < 4; j++) fma2(acc[i][j], ap, bp[j]);
            }
        }
        __syncthreads();
    }

    // epilogue: + bias, store h1, per-thread column stats
    float2 s2[4], q2[4];
#pragma unroll
    for (int j = 0; j < 4; j++) {
        s2[j] = make_float2(0.f, 0.f);
        q2[j] = make_float2(0.f, 0.f);
    }
#pragma unroll
    for (int j = 0; j < 4; j++) {
        int c0 = tx * 8 + 2 * j;
        float bx = bias[c0], by = bias[c0 + 1];
#pragma unroll
        for (int i = 0; i < 4; i++) {
            float2 v = unpack2(acc[i][j]);
            v.x += bx; v.y += by;
            *(float2*)&g_h1[(long long)(row0 + ty * 4 + i) * H + c0] = v;
            s2[j].x += v.x;       s2[j].y += v.y;
            q2[j].x += v.x * v.x; q2[j].y += v.y * v.y;
        }
    }
#pragma unroll
    for (int j = 0; j < 4; j++) *(float2*)&red[ty][tx * 8 + 2 * j] = s2[j];
    __syncthreads();
    if (tid < 128) {
        float s = 0.f;
#pragma unroll
        for (int t = 0; t < 16; t++) s += red[t][tid];
        atomicAdd(&g_sum[tid], s);
    }
    __syncthreads();
#pragma unroll
    for (int j = 0; j < 4; j++) *(float2*)&red[ty][tx * 8 + 2 * j] = q2[j];
    __syncthreads();
    if (tid < 128) {
        float s = 0.f;
#pragma unroll
        for (int t = 0; t < 16; t++) s += red[t][tid];
        atomicAdd(&g_sumsq[tid], s);
    }
}

// ============================================================================
// Edge GEMM2 + scatter: agg[col[e]] += relu(BN(h1[e])) @ W2a + b2a
// ============================================================================
__global__ __launch_bounds__(256) void edge_gemm2_scatter(
    const int* __restrict__ ei, const float* __restrict__ W,
    const float* __restrict__ bias) {
    __shared__ float As[16][64];
    __shared__ float Ws[16][128];
    __shared__ int colidx[64];

    const int tid = threadIdx.x;
    const int tx = tid & 15, ty = tid >> 4;
    const int row0 = blockIdx.x * 64;

    if (tid < 64) colidx[tid] = ei[NEDGES + row0 + tid];  // dest node
    __syncthreads();

    unsigned long long acc[4][4];
#pragma unroll
    for (int i = 0; i < 4; i++)
#pragma unroll
        for (int j = 0; j < 4; j++) acc[i][j] = 0ULL;

    const int lr = tid & 63;
    const int lk4 = (tid >> 6) << 2;

    for (int k0 = 0; k0 < 128; k0 += 16) {
        int kk = k0 + lk4;
        float4 v  = *(const float4*)&g_h1[(long long)(row0 + lr) * H + kk];
        float4 sc = *(const float4*)&g_scale[kk];
        float4 sh = *(const float4*)&g_shift[kk];
        v.x = fmaxf(fmaf(v.x, sc.x, sh.x), 0.f);
        v.y = fmaxf(fmaf(v.y, sc.y, sh.y), 0.f);
        v.z = fmaxf(fmaf(v.z, sc.z, sh.z), 0.f);
        v.w = fmaxf(fmaf(v.w, sc.w, sh.w), 0.f);
        As[lk4 + 0][lr] = v.x; As[lk4 + 1][lr] = v.y;
        As[lk4 + 2][lr] = v.z; As[lk4 + 3][lr] = v.w;

        int idx = tid * 8;
        int wkr = idx >> 7, wc = idx & 127;
        *(float4*)&Ws[wkr][wc]     = *(const float4*)&W[(k0 + wkr) * H + wc];
        *(float4*)&Ws[wkr][wc + 4] = *(const float4*)&W[(k0 + wkr) * H + wc + 4];
        __syncthreads();

#pragma unroll
        for (int k = 0; k < 16; k++) {
            float4 a4 = *(const float4*)&As[k][ty * 4];
            float4 b0 = *(const float4*)&Ws[k][tx * 8];
            float4 b1 = *(const float4*)&Ws[k][tx * 8 + 4];
            unsigned long long bp[4] = {pack2(b0.x, b0.y), pack2(b0.z, b0.w),
                                        pack2(b1.x, b1.y), pack2(b1.z, b1.w)};
            float ar[4] = {a4.x, a4.y, a4.z, a4.w};
#pragma unroll
            for (int i = 0; i < 4; i++) {
                unsigned long long ap = pack2(ar[i], ar[i]);
#pragma unroll
                for (int j = 0; j < 4; j++) fma2(acc[i][j], ap, bp[j]);
            }
        }
        __syncthreads();
    }

    // epilogue: + bias, atomic scatter-add into agg
#pragma unroll
    for (int i = 0; i < 4; i++) {
        int node = colidx[ty * 4 + i];
        float* dst = &g_agg[node * H];
#pragma unroll
        for (int j = 0; j < 4; j++) {
            int c0 = tx * 8 + 2 * j;
            float2 v = unpack2(acc[i][j]);
            atomicAdd(dst + c0,     v.x + bias[c0]);
            atomicAdd(dst + c0 + 1, v.y + bias[c0 + 1]);
        }
    }
}

// ============================================================================
// Node GEMM1: h2[n] = concat(x[n], agg[n]) @ W1b + b1b   (K = 192) + stats
// ============================================================================
__global__ __launch_bounds__(256) void node_gemm1(
    const float* __restrict__ x, const float* __restrict__ W,
    const float* __restrict__ bias) {
    __shared__ float As[16][64];
    __shared__ float Ws[16][128];
    __shared__ float red[16][128];

    const int tid = threadIdx.x;
    const int tx = tid & 15, ty = tid >> 4;
    const int row0 = blockIdx.x * 64;

    unsigned long long acc[4][4];
#pragma unroll
    for (int i = 0; i < 4; i++)
#pragma unroll
        for (int j = 0; j < 4; j++) acc[i][j] = 0ULL;

    const int lr = tid & 63;
    const int lk4 = (tid >> 6) << 2;
    const int n_load = row0 + lr;

    for (int k0 = 0; k0 < 192; k0 += 16) {
        int kk = k0 + lk4;
        float4 v = {0.f, 0.f, 0.f, 0.f};
        if (n_load < NNODES) {
            if (kk < 64)
                v = *(const float4*)&x[n_load * ND + kk];
            else
                v = *(const float4*)&g_agg[n_load * H + (kk - 64)];
        }
        As[lk4 + 0][lr] = v.x; As[lk4 + 1][lr] = v.y;
        As[lk4 + 2][lr] = v.z; As[lk4 + 3][lr] = v.w;

        int idx = tid * 8;
        int wkr = idx >> 7, wc = idx & 127;
        *(float4*)&Ws[wkr][wc]     = *(const float4*)&W[(k0 + wkr) * H + wc];
        *(float4*)&Ws[wkr][wc + 4] = *(const float4*)&W[(k0 + wkr) * H + wc + 4];
        __syncthreads();

#pragma unroll
        for (int k = 0; k < 16; k++) {
            float4 a4 = *(const float4*)&As[k][ty * 4];
            float4 b0 = *(const float4*)&Ws[k][tx * 8];
            float4 b1 = *(const float4*)&Ws[k][tx * 8 + 4];
            unsigned long long bp[4] = {pack2(b0.x, b0.y), pack2(b0.z, b0.w),
                                        pack2(b1.x, b1.y), pack2(b1.z, b1.w)};
            float ar[4] = {a4.x, a4.y, a4.z, a4.w};
#pragma unroll
            for (int i = 0; i < 4; i++) {
                unsigned long long ap = pack2(ar[i], ar[i]);
#pragma unroll
                for (int j = 0; j < 4; j++) fma2(acc[i][j], ap, bp[j]);
            }
        }
        __syncthreads();
    }

    float2 s2[4], q2[4];
#pragma unroll
    for (int j = 0; j < 4; j++) {
        s2[j] = make_float2(0.f, 0.f);
        q2[j] = make_float2(0.f, 0.f);
    }
#pragma unroll
    for (int i = 0; i < 4; i++) {
        int n = row0 + ty * 4 + i;
        if (n >= NNODES) continue;
#pragma unroll
        for (int j = 0; j < 4; j++) {
            int c0 = tx * 8 + 2 * j;
            float2 v = unpack2(acc[i][j]);
            v.x += bias[c0]; v.y += bias[c0 + 1];
            *(float2*)&g_h2[n * H + c0] = v;
            s2[j].x += v.x;       s2[j].y += v.y;
            q2[j].x += v.x * v.x; q2[j].y += v.y * v.y;
        }
    }
#pragma unroll
    for (int j = 0; j < 4; j++) *(float2*)&red[ty][tx * 8 + 2 * j] = s2[j];
    __syncthreads();
    if (tid < 128) {
        float s = 0.f;
#pragma unroll
        for (int t = 0; t < 16; t++) s += red[t][tid];
        atomicAdd(&g_sum[tid], s);
    }
    __syncthreads();
#pragma unroll
    for (int j = 0; j < 4; j++) *(float2*)&red[ty][tx * 8 + 2 * j] = q2[j];
    __syncthreads();
    if (tid < 128) {
        float s = 0.f;
#pragma unroll
        for (int t = 0; t < 16; t++) s += red[t][tid];
        atomicAdd(&g_sumsq[tid], s);
    }
}

// ============================================================================
// Node GEMM2: out[n] = relu(BN(h2[n])) @ W2b + b2b     (128 -> 64)
// tile 64 rows x 64 cols, thread microtile 4x4
// ============================================================================
__global__ __launch_bounds__(256) void node_gemm2(
    const float* __restrict__ W, const float* __restrict__ bias,
    float* __restrict__ out) {
    __shared__ float As[16][64];
    __shared__ float Ws[16][64];

    const int tid = threadIdx.x;
    const int tx = tid & 15, ty = tid >> 4;  // cols tx*4.., rows ty*4..
    const int row0 = blockIdx.x * 64;

    unsigned long long acc[4][2];
#pragma unroll
    for (int i = 0; i < 4; i++) { acc[i][0] = 0ULL; acc[i][1] = 0ULL; }

    const int lr = tid & 63;
    const int lk4 = (tid >> 6) << 2;
    const int n_load = row0 + lr;

    for (int k0 = 0; k0 < 128; k0 += 16) {
        int kk = k0 + lk4;
        float4 v = {0.f, 0.f, 0.f, 0.f};
        if (n_load < NNODES) {
            v = *(const float4*)&g_h2[n_load * H + kk];
            float4 sc = *(const float4*)&g_scale[kk];
            float4 sh = *(const float4*)&g_shift[kk];
            v.x = fmaxf(fmaf(v.x, sc.x, sh.x), 0.f);
            v.y = fmaxf(fmaf(v.y, sc.y, sh.y), 0.f);
            v.z = fmaxf(fmaf(v.z, sc.z, sh.z), 0.f);
            v.w = fmaxf(fmaf(v.w, sc.w, sh.w), 0.f);
        }
        As[lk4 + 0][lr] = v.x; As[lk4 + 1][lr] = v.y;
        As[lk4 + 2][lr] = v.z; As[lk4 + 3][lr] = v.w;

        int idx = tid * 4;
        int wkr = idx >> 6, wc = idx & 63;
        *(float4*)&Ws[wkr][wc] = *(const float4*)&W[(k0 + wkr) * OUTD + wc];
        __syncthreads();

#pragma unroll
        for (int k = 0; k < 16; k++) {
            float4 a4 = *(const float4*)&As[k][ty * 4];
            float4 b0 = *(const float4*)&Ws[k][tx * 4];
            unsigned long long bp[2] = {pack2(b0.x, b0.y), pack2(b0.z, b0.w)};
            float ar[4] = {a4.x, a4.y, a4.z, a4.w};
#pragma unroll
            for (int i = 0; i < 4; i++) {
                unsigned long long ap = pack2(ar[i], ar[i]);
                fma2(acc[i][0], ap, bp[0]);
                fma2(acc[i][1], ap, bp[1]);
            }
        }
        __syncthreads();
    }

#pragma unroll
    for (int i = 0; i < 4; i++) {
        int n = row0 + ty * 4 + i;
        if (n >= NNODES) continue;
#pragma unroll
        for (int j = 0; j < 2; j++) {
            int c0 = tx * 4 + 2 * j;
            float2 v = unpack2(acc[i][j]);
            v.x += bias[c0]; v.y += bias[c0 + 1];
            *(float2*)&out[n * OUTD + c0] = v;
        }
    }
}

// ============================================================================
extern "C" void kernel_launch(void* const* d_in, const int* in_sizes, int n_in,
                              void* d_out, int out_size) {
    const float* x    = (const float*)d_in[0];
    const int*   ei   = (const int*)d_in[1];
    const float* ea   = (const float*)d_in[2];
    // d_in[3] = u, d_in[4] = batch : unused by the node model
    const float* W1a  = (const float*)d_in[5];
    const float* b1a  = (const float*)d_in[6];
    const float* g1a  = (const float*)d_in[7];
    const float* be1a = (const float*)d_in[8];
    const float* W2a  = (const float*)d_in[9];
    const float* b2a  = (const float*)d_in[10];
    const float* W1b  = (const float*)d_in[11];
    const float* b1b  = (const float*)d_in[12];
    const float* g1b  = (const float*)d_in[13];
    const float* be1b = (const float*)d_in[14];
    const float* W2b  = (const float*)d_in[15];
    const float* b2b  = (const float*)d_in[16];
    float* out = (float*)d_out;

    const int edge_blocks = NEDGES / 64;            // 12500
    const int node_blocks = (NNODES + 63) / 64;     // 782

    zero_kernel<<<(NNODES * H / 4 + 255) / 256, 256>>>();
    edge_gemm1<<<edge_blocks, 256>>>(x, ei, ea, W1a, b1a);
    finalize_bn<<<1, 128>>>(g1a, be1a, 1.0f / (float)NEDGES);
    edge_gemm2_scatter<<<edge_blocks, 256>>>(ei, W2a, b2a);
    node_gemm1<<<node_blocks, 256>>>(x, W1b, b1b);
    finalize_bn<<<1, 128>>>(g1b, be1b, 1.0f / (float)NNODES);
    node_gemm2<<<node_blocks, 256>>>(W2b, b2b, out);
}

// round 5
// speedup vs baseline: 2.4284x; 2.4284x over previous
#include <cuda_runtime.h>
#include <cuda_bf16.h>
#include <cstdint>

#define NNODES 50000
#define NEDGES 800000
#define ND     64
#define H      128
#define OUTD   64
#define BN_EPS 1e-5f

// ---------------- scratch (device globals; no allocations allowed) ----------
__device__ float g_h1[(size_t)NEDGES * H];     // [edge][col]
__device__ float g_agg[(size_t)NNODES * H];
__device__ float g_h2[(size_t)NNODES * H];
__device__ float g_sum[H];
__device__ float g_sumsq[H];
__device__ float g_scale[H];
__device__ float g_shift[H];
// pre-split transposed weights: word (n, kpair) = bf16{k even}|bf16{k odd}<<16
__device__ __align__(16) uint32_t g_W1T_hi[128 * 64];
__device__ __align__(16) uint32_t g_W1T_lo[128 * 64];
__device__ __align__(16) uint32_t g_W2T_hi[128 * 64];
__device__ __align__(16) uint32_t g_W2T_lo[128 * 64];

// ---------------- helpers ----------------------------------------------------
__device__ __forceinline__ void split2(float a, float b, uint32_t& hi, uint32_t& lo) {
    __nv_bfloat16 ah = __float2bfloat16_rn(a), bh = __float2bfloat16_rn(b);
    float ar = a - __bfloat162float(ah);
    float br = b - __bfloat162float(bh);
    __nv_bfloat16 al = __float2bfloat16_rn(ar), bl = __float2bfloat16_rn(br);
    hi = (uint32_t)__bfloat16_as_ushort(ah) | ((uint32_t)__bfloat16_as_ushort(bh) << 16);
    lo = (uint32_t)__bfloat16_as_ushort(al) | ((uint32_t)__bfloat16_as_ushort(bl) << 16);
}

__device__ __forceinline__ void mma16816(float* c, const uint32_t* a, const uint32_t* b) {
    asm volatile(
        "mma.sync.aligned.m16n8k16.row.col.f32.bf16.bf16.f32 "
        "{%0,%1,%2,%3}, {%4,%5,%6,%7}, {%8,%9}, {%0,%1,%2,%3};"
        : "+f"(c[0]), "+f"(c[1]), "+f"(c[2]), "+f"(c[3])
        : "r"(a[0]), "r"(a[1]), "r"(a[2]), "r"(a[3]), "r"(b[0]), "r"(b[1]));
}

// S = smem stride in words (kpairs + 4 pad). 16 kpairs (32 k) per chunk.
#define SK 20

// per-chunk mma: warp tile 32(M) x 32(N), 2 sub-steps of k16
__device__ __forceinline__ void mma_chunk(
    const uint32_t* __restrict__ sAh, const uint32_t* __restrict__ sAl,
    const uint32_t* __restrict__ sBh, const uint32_t* __restrict__ sBl,
    int wm, int wn, int g, int t4, float acc[2][4][4]) {
#pragma unroll
    for (int kc = 0; kc < 16; kc += 8) {
        uint32_t ah[2][4], al[2][4], bh[4][2], bl[4][2];
#pragma unroll
        for (int mt = 0; mt < 2; mt++) {
            int base = (wm + mt * 16 + g) * SK + kc + t4;
            ah[mt][0] = sAh[base];          ah[mt][1] = sAh[base + 8 * SK];
            ah[mt][2] = sAh[base + 4];      ah[mt][3] = sAh[base + 8 * SK + 4];
            al[mt][0] = sAl[base];          al[mt][1] = sAl[base + 8 * SK];
            al[mt][2] = sAl[base + 4];      al[mt][3] = sAl[base + 8 * SK + 4];
        }
#pragma unroll
        for (int nt = 0; nt < 4; nt++) {
            int nb = (wn + nt * 8 + g) * SK + kc + t4;
            bh[nt][0] = sBh[nb]; bh[nt][1] = sBh[nb + 4];
            bl[nt][0] = sBl[nb]; bl[nt][1] = sBl[nb + 4];
        }
#pragma unroll
        for (int mt = 0; mt < 2; mt++)
#pragma unroll
            for (int nt = 0; nt < 4; nt++) mma16816(acc[mt][nt], ah[mt], bh[nt]);
#pragma unroll
        for (int mt = 0; mt < 2; mt++)
#pragma unroll
            for (int nt = 0; nt < 4; nt++) mma16816(acc[mt][nt], ah[mt], bl[nt]);
#pragma unroll
        for (int mt = 0; mt < 2; mt++)
#pragma unroll
            for (int nt = 0; nt < 4; nt++) mma16816(acc[mt][nt], al[mt], bh[nt]);
    }
}

// ---------------- small kernels ----------------------------------------------
__global__ void zero_kernel() {
    int i = blockIdx.x * blockDim.x + threadIdx.x;
    const float4 z = {0.f, 0.f, 0.f, 0.f};
    if (i < NNODES * H / 4) ((float4*)g_agg)[i] = z;
    if (i < H / 4) { ((float4*)g_sum)[i] = z; ((float4*)g_sumsq)[i] = z; }
}

__global__ void finalize_bn(const float* __restrict__ gamma,
                            const float* __restrict__ beta, float invM) {
    int c = threadIdx.x;
    float mean = g_sum[c] * invM;
    float var  = g_sumsq[c] * invM - mean * mean;
    float sc   = gamma[c] * rsqrtf(var + BN_EPS);
    g_scale[c] = sc;
    g_shift[c] = beta[c] - mean * sc;
    g_sum[c] = 0.f; g_sumsq[c] = 0.f;
}

// transpose+split W[128][128] -> hi/lo words [n][kpair0..63]
// Destination resolved in DEVICE code (passing __device__ globals as kernel
// args from host is invalid — that was the round-3/4 bug).
__global__ void wsplit(const float* __restrict__ W, int which) {
    uint32_t* hi = (which == 0) ? g_W1T_hi : g_W2T_hi;
    uint32_t* lo = (which == 0) ? g_W1T_lo : g_W2T_lo;
    int i = blockIdx.x * 256 + threadIdx.x;   // 8192 total
    if (i >= 128 * 64) return;
    int n = i >> 6, kp = i & 63;
    float a = W[(2 * kp) * 128 + n];
    float b = W[(2 * kp + 1) * 128 + n];
    uint32_t h, l;
    split2(a, b, h, l);
    hi[i] = h; lo[i] = l;
}

// ============================================================================
// Edge GEMM1: h1 = concat(x[row], ea) @ W1a + b1a ; fused BN stats.
// 64(M) x 128(N) tile, K=128 in 4 chunks of 32. 256 threads, static smem.
// ============================================================================
__global__ __launch_bounds__(256) void edge_mma1(
    const float* __restrict__ x, const int* __restrict__ ei,
    const float* __restrict__ ea, const float* __restrict__ bias) {
    __shared__ uint32_t sAh[64 * SK], sAl[64 * SK];
    __shared__ uint32_t sBh[128 * SK], sBl[128 * SK];
    __shared__ int rowidx[64];
    __shared__ float s_bias[128];
    __shared__ float red_s[2][128], red_q[2][128];

    const int t = threadIdx.x, tile = blockIdx.x;
    if (t < 64) rowidx[t] = ei[tile * 64 + t];
    if (t < 128) s_bias[t] = bias[t];
    __syncthreads();

    const int warp = t >> 5, lane = t & 31, g = lane >> 2, t4 = lane & 3;
    const int wm = (warp >> 2) * 32, wn = (warp & 3) * 32;
    const int m = t >> 2, q = t & 3;       // A loader coords
    const int n = t >> 1, half = t & 1;    // B loader coords

    float acc[2][4][4];
#pragma unroll
    for (int i = 0; i < 2; i++)
#pragma unroll
        for (int j = 0; j < 4; j++)
#pragma unroll
            for (int k = 0; k < 4; k++) acc[i][j][k] = 0.f;

#pragma unroll
    for (int s = 0; s < 4; s++) {
        {   // A chunk: rows x cols [s*32, s*32+32)
            int kb = s * 32 + q * 8;
            const float* src = (s < 2) ? (x + (size_t)rowidx[m] * ND + kb)
                                       : (ea + (size_t)(tile * 64 + m) * ND + (kb - 64));
            float4 v0 = ((const float4*)src)[0];
            float4 v1 = ((const float4*)src)[1];
            uint32_t h0, l0, h1, l1, h2, l2, h3, l3;
            split2(v0.x, v0.y, h0, l0); split2(v0.z, v0.w, h1, l1);
            split2(v1.x, v1.y, h2, l2); split2(v1.z, v1.w, h3, l3);
            uint32_t* dh = &sAh[m * SK + q * 4];
            uint32_t* dl = &sAl[m * SK + q * 4];
            dh[0] = h0; dh[1] = h1; dh[2] = h2; dh[3] = h3;
            dl[0] = l0; dl[1] = l1; dl[2] = l2; dl[3] = l3;
        }
        {   // B chunk: pre-split words, kpairs [s*16, s*16+16)
            const uint4* pH = (const uint4*)&g_W1T_hi[n * 64 + s * 16 + half * 8];
            const uint4* pL = (const uint4*)&g_W1T_lo[n * 64 + s * 16 + half * 8];
            uint4 a0 = pH[0], a1 = pH[1], b0 = pL[0], b1 = pL[1];
            uint32_t* dh = &sBh[n * SK + half * 8];
            uint32_t* dl = &sBl[n * SK + half * 8];
            dh[0] = a0.x; dh[1] = a0.y; dh[2] = a0.z; dh[3] = a0.w;
            dh[4] = a1.x; dh[5] = a1.y; dh[6] = a1.z; dh[7] = a1.w;
            dl[0] = b0.x; dl[1] = b0.y; dl[2] = b0.z; dl[3] = b0.w;
            dl[4] = b1.x; dl[5] = b1.y; dl[6] = b1.z; dl[7] = b1.w;
        }
        __syncthreads();
        mma_chunk(sAh, sAl, sBh, sBl, wm, wn, g, t4, acc);
        __syncthreads();
    }

    // epilogue: +bias, store h1, column stats
    float s8[8] = {0, 0, 0, 0, 0, 0, 0, 0}, q8[8] = {0, 0, 0, 0, 0, 0, 0, 0};
#pragma unroll
    for (int mt = 0; mt < 2; mt++) {
        int r0 = wm + mt * 16 + g;
#pragma unroll
        for (int nt = 0; nt < 4; nt++) {
            int c = wn + nt * 8 + 2 * t4;
            float bx = s_bias[c], by = s_bias[c + 1];
            float v00 = acc[mt][nt][0] + bx, v01 = acc[mt][nt][1] + by;
            float v10 = acc[mt][nt][2] + bx, v11 = acc[mt][nt][3] + by;
            size_t e0 = (size_t)(tile * 64 + r0) * H + c;
            float2 w0 = {v00, v01}, w1 = {v10, v11};
            *(float2*)&g_h1[e0] = w0;
            *(float2*)&g_h1[e0 + (size_t)8 * H] = w1;
            s8[nt * 2]     += v00 + v10;
            s8[nt * 2 + 1] += v01 + v11;
            q8[nt * 2]     += v00 * v00 + v10 * v10;
            q8[nt * 2 + 1] += v01 * v01 + v11 * v11;
        }
    }
#pragma unroll
    for (int j = 0; j < 8; j++)
#pragma unroll
        for (int o = 4; o < 32; o <<= 1) {
            s8[j] += __shfl_xor_sync(0xffffffffu, s8[j], o);
            q8[j] += __shfl_xor_sync(0xffffffffu, q8[j], o);
        }
    if (lane < 4) {
        int wr = warp >> 2;
#pragma unroll
        for (int nt = 0; nt < 4; nt++) {
            red_s[wr][wn + nt * 8 + 2 * lane]     = s8[nt * 2];
            red_s[wr][wn + nt * 8 + 2 * lane + 1] = s8[nt * 2 + 1];
            red_q[wr][wn + nt * 8 + 2 * lane]     = q8[nt * 2];
            red_q[wr][wn + nt * 8 + 2 * lane + 1] = q8[nt * 2 + 1];
        }
    }
    __syncthreads();
    if (t < 128) {
        atomicAdd(&g_sum[t],   red_s[0][t] + red_s[1][t]);
        atomicAdd(&g_sumsq[t], red_q[0][t] + red_q[1][t]);
    }
}

// ============================================================================
// Edge GEMM2 + scatter: agg[col] += relu(BN(h1)) @ W2a + b2a
// ============================================================================
__global__ __launch_bounds__(256) void edge_mma2(
    const int* __restrict__ ei, const float* __restrict__ bias) {
    __shared__ uint32_t sAh[64 * SK], sAl[64 * SK];
    __shared__ uint32_t sBh[128 * SK], sBl[128 * SK];
    __shared__ int colidx[64];
    __shared__ float s_bias[128], s_sc[128], s_sh[128];

    const int t = threadIdx.x, tile = blockIdx.x;
    if (t < 64) colidx[t] = ei[NEDGES + tile * 64 + t];
    if (t < 128) { s_bias[t] = bias[t]; s_sc[t] = g_scale[t]; s_sh[t] = g_shift[t]; }
    __syncthreads();

    const int warp = t >> 5, lane = t & 31, g = lane >> 2, t4 = lane & 3;
    const int wm = (warp >> 2) * 32, wn = (warp & 3) * 32;
    const int m = t >> 2, q = t & 3;
    const int n = t >> 1, half = t & 1;

    float acc[2][4][4];
#pragma unroll
    for (int i = 0; i < 2; i++)
#pragma unroll
        for (int j = 0; j < 4; j++)
#pragma unroll
            for (int k = 0; k < 4; k++) acc[i][j][k] = 0.f;

#pragma unroll
    for (int s = 0; s < 4; s++) {
        {   // A: BN+relu(h1) chunk
            int kb = s * 32 + q * 8;
            const float* src = g_h1 + (size_t)(tile * 64 + m) * H + kb;
            float4 v0 = ((const float4*)src)[0];
            float4 v1 = ((const float4*)src)[1];
            v0.x = fmaxf(fmaf(v0.x, s_sc[kb],     s_sh[kb]),     0.f);
            v0.y = fmaxf(fmaf(v0.y, s_sc[kb + 1], s_sh[kb + 1]), 0.f);
            v0.z = fmaxf(fmaf(v0.z, s_sc[kb + 2], s_sh[kb + 2]), 0.f);
            v0.w = fmaxf(fmaf(v0.w, s_sc[kb + 3], s_sh[kb + 3]), 0.f);
            v1.x = fmaxf(fmaf(v1.x, s_sc[kb + 4], s_sh[kb + 4]), 0.f);
            v1.y = fmaxf(fmaf(v1.y, s_sc[kb + 5], s_sh[kb + 5]), 0.f);
            v1.z = fmaxf(fmaf(v1.z, s_sc[kb + 6], s_sh[kb + 6]), 0.f);
            v1.w = fmaxf(fmaf(v1.w, s_sc[kb + 7], s_sh[kb + 7]), 0.f);
            uint32_t h0, l0, h1, l1, h2, l2, h3, l3;
            split2(v0.x, v0.y, h0, l0); split2(v0.z, v0.w, h1, l1);
            split2(v1.x, v1.y, h2, l2); split2(v1.z, v1.w, h3, l3);
            uint32_t* dh = &sAh[m * SK + q * 4];
            uint32_t* dl = &sAl[m * SK + q * 4];
            dh[0] = h0; dh[1] = h1; dh[2] = h2; dh[3] = h3;
            dl[0] = l0; dl[1] = l1; dl[2] = l2; dl[3] = l3;
        }
        {   // B
            const uint4* pH = (const uint4*)&g_W2T_hi[n * 64 + s * 16 + half * 8];
            const uint4* pL = (const uint4*)&g_W2T_lo[n * 64 + s * 16 + half * 8];
            uint4 a0 = pH[0], a1 = pH[1], b0 = pL[0], b1 = pL[1];
            uint32_t* dh = &sBh[n * SK + half * 8];
            uint32_t* dl = &sBl[n * SK + half * 8];
            dh[0] = a0.x; dh[1] = a0.y; dh[2] = a0.z; dh[3] = a0.w;
            dh[4] = a1.x; dh[5] = a1.y; dh[6] = a1.z; dh[7] = a1.w;
            dl[0] = b0.x; dl[1] = b0.y; dl[2] = b0.z; dl[3] = b0.w;
            dl[4] = b1.x; dl[5] = b1.y; dl[6] = b1.z; dl[7] = b1.w;
        }
        __syncthreads();
        mma_chunk(sAh, sAl, sBh, sBl, wm, wn, g, t4, acc);
        __syncthreads();
    }

    // epilogue: + bias, atomic scatter-add
#pragma unroll
    for (int mt = 0; mt < 2; mt++) {
        int r0 = wm + mt * 16 + g;
        int n0 = colidx[r0], n1 = colidx[r0 + 8];
#pragma unroll
        for (int nt = 0; nt < 4; nt++) {
            int c = wn + nt * 8 + 2 * t4;
            float bx = s_bias[c], by = s_bias[c + 1];
            atomicAdd(&g_agg[(size_t)n0 * H + c],     acc[mt][nt][0] + bx);
            atomicAdd(&g_agg[(size_t)n0 * H + c + 1], acc[mt][nt][1] + by);
            atomicAdd(&g_agg[(size_t)n1 * H + c],     acc[mt][nt][2] + bx);
            atomicAdd(&g_agg[(size_t)n1 * H + c + 1], acc[mt][nt][3] + by);
        }
    }
}

// ---------------- f32x2 helpers (node-side SIMT kernels, proven in R1) -------
__device__ __forceinline__ unsigned long long pack2(float a, float b) {
    unsigned long long r; asm("mov.b64 %0, {%1, %2};" : "=l"(r) : "f"(a), "f"(b)); return r;
}
__device__ __forceinline__ void fma2(unsigned long long& d, unsigned long long a,
                                     unsigned long long b) {
    asm("fma.rn.f32x2 %0, %1, %2, %0;" : "+l"(d) : "l"(a), "l"(b));
}
__device__ __forceinline__ float2 unpack2(unsigned long long v) {
    float2 f; asm("mov.b64 {%0, %1}, %2;" : "=f"(f.x), "=f"(f.y) : "l"(v)); return f;
}

// ============================================================================
// Node GEMM1 (SIMT, proven R1): h2 = concat(x, agg) @ W1b + b1b + stats
// ============================================================================
__global__ __launch_bounds__(256) void node_gemm1(
    const float* __restrict__ x, const float* __restrict__ W,
    const float* __restrict__ bias) {
    __shared__ float As[16][64];
    __shared__ float Ws[16][128];
    __shared__ float red[16][128];

    const int tid = threadIdx.x;
    const int tx = tid & 15, ty = tid >> 4;
    const int row0 = blockIdx.x * 64;

    unsigned long long acc[4][4];
#pragma unroll
    for (int i = 0; i < 4; i++)
#pragma unroll
        for (int j = 0; j < 4; j++) acc[i][j] = 0ULL;

    const int lr = tid & 63;
    const int lk4 = (tid >> 6) << 2;
    const int n_load = row0 + lr;

    for (int k0 = 0; k0 < 192; k0 += 16) {
        int kk = k0 + lk4;
        float4 v = {0.f, 0.f, 0.f, 0.f};
        if (n_load < NNODES) {
            if (kk < 64) v = *(const float4*)&x[(size_t)n_load * ND + kk];
            else         v = *(const float4*)&g_agg[(size_t)n_load * H + (kk - 64)];
        }
        As[lk4 + 0][lr] = v.x; As[lk4 + 1][lr] = v.y;
        As[lk4 + 2][lr] = v.z; As[lk4 + 3][lr] = v.w;

        int idx = tid * 8, wkr = idx >> 7, wc = idx & 127;
        *(float4*)&Ws[wkr][wc]     = *(const float4*)&W[(k0 + wkr) * H + wc];
        *(float4*)&Ws[wkr][wc + 4] = *(const float4*)&W[(k0 + wkr) * H + wc + 4];
        __syncthreads();

#pragma unroll
        for (int k = 0; k < 16; k++) {
            float4 a4 = *(const float4*)&As[k][ty * 4];
            float4 b0 = *(const float4*)&Ws[k][tx * 8];
            float4 b1 = *(const float4*)&Ws[k][tx * 8 + 4];
            unsigned long long bp[4] = {pack2(b0.x, b0.y), pack2(b0.z, b0.w),
                                        pack2(b1.x, b1.y), pack2(b1.z, b1.w)};
            float ar[4] = {a4.x, a4.y, a4.z, a4.w};
#pragma unroll
            for (int i = 0; i < 4; i++) {
                unsigned long long ap = pack2(ar[i], ar[i]);
#pragma unroll
                for (int j = 0; j < 4; j++) fma2(acc[i][j], ap, bp[j]);
            }
        }
        __syncthreads();
    }

    float2 s2[4], q2[4];
#pragma unroll
    for (int j = 0; j < 4; j++) { s2[j] = make_float2(0.f, 0.f); q2[j] = make_float2(0.f, 0.f); }
#pragma unroll
    for (int i = 0; i < 4; i++) {
        int nn = row0 + ty * 4 + i;
        if (nn >= NNODES) continue;
#pragma unroll
        for (int j = 0; j < 4; j++) {
            int c0 = tx * 8 + 2 * j;
            float2 v = unpack2(acc[i][j]);
            v.x += bias[c0]; v.y += bias[c0 + 1];
            *(float2*)&g_h2[(size_t)nn * H + c0] = v;
            s2[j].x += v.x; s2[j].y += v.y;
            q2[j].x += v.x * v.x; q2[j].y += v.y * v.y;
        }
    }
#pragma unroll
    for (int j = 0; j < 4; j++) *(float2*)&red[ty][tx * 8 + 2 * j] = s2[j];
    __syncthreads();
    if (tid < 128) {
        float s = 0.f;
#pragma unroll
        for (int tt = 0; tt < 16; tt++) s += red[tt][tid];
        atomicAdd(&g_sum[tid], s);
    }
    __syncthreads();
#pragma unroll
    for (int j = 0; j < 4; j++) *(float2*)&red[ty][tx * 8 + 2 * j] = q2[j];
    __syncthreads();
    if (tid < 128) {
        float s = 0.f;
#pragma unroll
        for (int tt = 0; tt < 16; tt++) s += red[tt][tid];
        atomicAdd(&g_sumsq[tid], s);
    }
}

// ============================================================================
// Node GEMM2 (SIMT, proven R1): out = relu(BN(h2)) @ W2b + b2b
// ============================================================================
__global__ __launch_bounds__(256) void node_gemm2(
    const float* __restrict__ W, const float* __restrict__ bias,
    float* __restrict__ out) {
    __shared__ float As[16][64];
    __shared__ float Ws[16][64];

    const int tid = threadIdx.x;
    const int tx = tid & 15, ty = tid >> 4;
    const int row0 = blockIdx.x * 64;

    unsigned long long acc[4][2];
#pragma unroll
    for (int i = 0; i < 4; i++) { acc[i][0] = 0ULL; acc[i][1] = 0ULL; }

    const int lr = tid & 63;
    const int lk4 = (tid >> 6) << 2;
    const int n_load = row0 + lr;

    for (int k0 = 0; k0 < 128; k0 += 16) {
        int kk = k0 + lk4;
        float4 v = {0.f, 0.f, 0.f, 0.f};
        if (n_load < NNODES) {
            v = *(const float4*)&g_h2[(size_t)n_load * H + kk];
            float4 sc = *(const float4*)&g_scale[kk];
            float4 sh = *(const float4*)&g_shift[kk];
            v.x = fmaxf(fmaf(v.x, sc.x, sh.x), 0.f);
            v.y = fmaxf(fmaf(v.y, sc.y, sh.y), 0.f);
            v.z = fmaxf(fmaf(v.z, sc.z, sh.z), 0.f);
            v.w = fmaxf(fmaf(v.w, sc.w, sh.w), 0.f);
        }
        As[lk4 + 0][lr] = v.x; As[lk4 + 1][lr] = v.y;
        As[lk4 + 2][lr] = v.z; As[lk4 + 3][lr] = v.w;

        int idx = tid * 4, wkr = idx >> 6, wc = idx & 63;
        *(float4*)&Ws[wkr][wc] = *(const float4*)&W[(k0 + wkr) * OUTD + wc];
        __syncthreads();

#pragma unroll
        for (int k = 0; k < 16; k++) {
            float4 a4 = *(const float4*)&As[k][ty * 4];
            float4 b0 = *(const float4*)&Ws[k][tx * 4];
            unsigned long long bp[2] = {pack2(b0.x, b0.y), pack2(b0.z, b0.w)};
            float ar[4] = {a4.x, a4.y, a4.z, a4.w};
#pragma unroll
            for (int i = 0; i < 4; i++) {
                unsigned long long ap = pack2(ar[i], ar[i]);
                fma2(acc[i][0], ap, bp[0]);
                fma2(acc[i][1], ap, bp[1]);
            }
        }
        __syncthreads();
    }

#pragma unroll
    for (int i = 0; i < 4; i++) {
        int nn = row0 + ty * 4 + i;
        if (nn >= NNODES) continue;
#pragma unroll
        for (int j = 0; j < 2; j++) {
            int c0 = tx * 4 + 2 * j;
            float2 v = unpack2(acc[i][j]);
            v.x += bias[c0]; v.y += bias[c0 + 1];
            *(float2*)&out[(size_t)nn * OUTD + c0] = v;
        }
    }
}

// ============================================================================
extern "C" void kernel_launch(void* const* d_in, const int* in_sizes, int n_in,
                              void* d_out, int out_size) {
    const float* x    = (const float*)d_in[0];
    const int*   ei   = (const int*)d_in[1];
    const float* ea   = (const float*)d_in[2];
    const float* W1a  = (const float*)d_in[5];
    const float* b1a  = (const float*)d_in[6];
    const float* g1a  = (const float*)d_in[7];
    const float* be1a = (const float*)d_in[8];
    const float* W2a  = (const float*)d_in[9];
    const float* b2a  = (const float*)d_in[10];
    const float* W1b  = (const float*)d_in[11];
    const float* b1b  = (const float*)d_in[12];
    const float* g1b  = (const float*)d_in[13];
    const float* be1b = (const float*)d_in[14];
    const float* W2b  = (const float*)d_in[15];
    const float* b2b  = (const float*)d_in[16];
    float* out = (float*)d_out;

    const int edge_tiles = NEDGES / 64;          // 12500
    const int node_blocks = (NNODES + 63) / 64;  // 782

    zero_kernel<<<(NNODES * H / 4 + 255) / 256, 256>>>();
    wsplit<<<32, 256>>>(W1a, 0);
    wsplit<<<32, 256>>>(W2a, 1);

    edge_mma1<<<edge_tiles, 256>>>(x, ei, ea, b1a);
    finalize_bn<<<1, 128>>>(g1a, be1a, 1.0f / (float)NEDGES);
    edge_mma2<<<edge_tiles, 256>>>(ei, b2a);
    node_gemm1<<<node_blocks, 256>>>(x, W1b, b1b);
    finalize_bn<<<1, 128>>>(g1b, be1b, 1.0f / (float)NNODES);
    node_gemm2<<<node_blocks, 256>>>(W2b, b2b, out);
}

// round 6
// speedup vs baseline: 2.6101x; 1.0748x over previous
#include <cuda_runtime.h>
#include <cuda_bf16.h>
#include <cstdint>

#define NNODES 50000
#define NEDGES 800000
#define ND     64
#define H      128
#define OUTD   64
#define BN_EPS 1e-5f

// ---------------- scratch (device globals; no allocations allowed) ----------
__device__ float g_h1[(size_t)NEDGES * H];     // [edge][col]
__device__ float g_agg[(size_t)NNODES * H];
__device__ float g_h2[(size_t)NNODES * H];
__device__ float g_sum[H];
__device__ float g_sumsq[H];
__device__ float g_scale[H];
__device__ float g_shift[H];
// pre-split transposed weights: word (n, kpair) = bf16{k even}|bf16{k odd}<<16
__device__ __align__(16) uint32_t g_W1T_hi[128 * 64];
__device__ __align__(16) uint32_t g_W1T_lo[128 * 64];
__device__ __align__(16) uint32_t g_W2T_hi[128 * 64];
__device__ __align__(16) uint32_t g_W2T_lo[128 * 64];

// ---------------- helpers ----------------------------------------------------
__device__ __forceinline__ void split2(float a, float b, uint32_t& hi, uint32_t& lo) {
    __nv_bfloat16 ah = __float2bfloat16_rn(a), bh = __float2bfloat16_rn(b);
    float ar = a - __bfloat162float(ah);
    float br = b - __bfloat162float(bh);
    __nv_bfloat16 al = __float2bfloat16_rn(ar), bl = __float2bfloat16_rn(br);
    hi = (uint32_t)__bfloat16_as_ushort(ah) | ((uint32_t)__bfloat16_as_ushort(bh) << 16);
    lo = (uint32_t)__bfloat16_as_ushort(al) | ((uint32_t)__bfloat16_as_ushort(bl) << 16);
}

__device__ __forceinline__ void mma4(float* c, const uint32_t* a, uint32_t b0, uint32_t b1) {
    asm volatile(
        "mma.sync.aligned.m16n8k16.row.col.f32.bf16.bf16.f32 "
        "{%0,%1,%2,%3}, {%4,%5,%6,%7}, {%8,%9}, {%0,%1,%2,%3};"
        : "+f"(c[0]), "+f"(c[1]), "+f"(c[2]), "+f"(c[3])
        : "r"(a[0]), "r"(a[1]), "r"(a[2]), "r"(a[3]), "r"(b0), "r"(b1));
}

__device__ __forceinline__ void ldsm4(uint32_t* r, uint32_t addr) {
    asm volatile("ldmatrix.sync.aligned.m8n8.x4.shared.b16 {%0,%1,%2,%3}, [%4];"
                 : "=r"(r[0]), "=r"(r[1]), "=r"(r[2]), "=r"(r[3]) : "r"(addr));
}

__device__ __forceinline__ uint32_t smaddr(const void* p) {
    return (uint32_t)__cvta_generic_to_shared(p);
}

// smem stride in words (16 kpairs + 4 pad); LDSM-conflict-free (20r mod 32 distinct)
#define SK 20

// One k32 chunk of bf16x3 MMA using ldmatrix feeds.
// aH0/aH1/... : per-lane LDSM base addresses (bytes) for mt=0/1 (A) and j=0/1 (B).
__device__ __forceinline__ void mma_chunk_ldsm(
    uint32_t aH0, uint32_t aH1, uint32_t aL0, uint32_t aL1,
    uint32_t bH0, uint32_t bH1, uint32_t bL0, uint32_t bL1,
    float acc[2][4][4]) {
#pragma unroll
    for (int kc = 0; kc < 2; kc++) {
        const uint32_t kb = kc * 32;   // 8 words = k16
        uint32_t a0[4], a1[4], b0[4], b1[4];
        ldsm4(a0, aH0 + kb); ldsm4(a1, aH1 + kb);
        ldsm4(b0, bH0 + kb); ldsm4(b1, bH1 + kb);
        // hi * hi
        mma4(acc[0][0], a0, b0[0], b0[2]); mma4(acc[0][1], a0, b0[1], b0[3]);
        mma4(acc[0][2], a0, b1[0], b1[2]); mma4(acc[0][3], a0, b1[1], b1[3]);
        mma4(acc[1][0], a1, b0[0], b0[2]); mma4(acc[1][1], a1, b0[1], b0[3]);
        mma4(acc[1][2], a1, b1[0], b1[2]); mma4(acc[1][3], a1, b1[1], b1[3]);
        // hi * lo
        uint32_t c0[4], c1[4];
        ldsm4(c0, bL0 + kb); ldsm4(c1, bL1 + kb);
        mma4(acc[0][0], a0, c0[0], c0[2]); mma4(acc[0][1], a0, c0[1], c0[3]);
        mma4(acc[0][2], a0, c1[0], c1[2]); mma4(acc[0][3], a0, c1[1], c1[3]);
        mma4(acc[1][0], a1, c0[0], c0[2]); mma4(acc[1][1], a1, c0[1], c0[3]);
        mma4(acc[1][2], a1, c1[0], c1[2]); mma4(acc[1][3], a1, c1[1], c1[3]);
        // lo * hi
        uint32_t d0[4], d1[4];
        ldsm4(d0, aL0 + kb); ldsm4(d1, aL1 + kb);
        mma4(acc[0][0], d0, b0[0], b0[2]); mma4(acc[0][1], d0, b0[1], b0[3]);
        mma4(acc[0][2], d0, b1[0], b1[2]); mma4(acc[0][3], d0, b1[1], b1[3]);
        mma4(acc[1][0], d1, b0[0], b0[2]); mma4(acc[1][1], d1, b0[1], b0[3]);
        mma4(acc[1][2], d1, b1[0], b1[2]); mma4(acc[1][3], d1, b1[1], b1[3]);
    }
}

// ---------------- small kernels ----------------------------------------------
__global__ void zero_kernel() {
    int i = blockIdx.x * blockDim.x + threadIdx.x;
    const float4 z = {0.f, 0.f, 0.f, 0.f};
    if (i < NNODES * H / 4) ((float4*)g_agg)[i] = z;
    if (i < H / 4) { ((float4*)g_sum)[i] = z; ((float4*)g_sumsq)[i] = z; }
}

__global__ void finalize_bn(const float* __restrict__ gamma,
                            const float* __restrict__ beta, float invM) {
    int c = threadIdx.x;
    float mean = g_sum[c] * invM;
    float var  = g_sumsq[c] * invM - mean * mean;
    float sc   = gamma[c] * rsqrtf(var + BN_EPS);
    g_scale[c] = sc;
    g_shift[c] = beta[c] - mean * sc;
    g_sum[c] = 0.f; g_sumsq[c] = 0.f;
}

// transpose+split W[128][128] -> hi/lo words [n][kpair0..63] (device-resolved dst)
__global__ void wsplit(const float* __restrict__ W, int which) {
    uint32_t* hi = (which == 0) ? g_W1T_hi : g_W2T_hi;
    uint32_t* lo = (which == 0) ? g_W1T_lo : g_W2T_lo;
    int i = blockIdx.x * 256 + threadIdx.x;
    if (i >= 128 * 64) return;
    int n = i >> 6, kp = i & 63;
    float a = W[(2 * kp) * 128 + n];
    float b = W[(2 * kp + 1) * 128 + n];
    uint32_t h, l;
    split2(a, b, h, l);
    hi[i] = h; lo[i] = l;
}

// ============================================================================
// Edge GEMM1: h1 = concat(x[row], ea) @ W1a + b1a ; fused BN stats.
// 64(M) x 128(N), K=128 in 4 chunks of 32; LDSM feeds + global prefetch.
// ============================================================================
__global__ __launch_bounds__(256, 2) void edge_mma1(
    const float* __restrict__ x, const int* __restrict__ ei,
    const float* __restrict__ ea, const float* __restrict__ bias) {
    __shared__ uint32_t sAh[64 * SK], sAl[64 * SK];
    __shared__ uint32_t sBh[128 * SK], sBl[128 * SK];
    __shared__ int rowidx[64];
    __shared__ float s_bias[128];
    __shared__ float red_s[2][128], red_q[2][128];

    const int t = threadIdx.x, tile = blockIdx.x;
    if (t < 64) rowidx[t] = ei[tile * 64 + t];
    if (t < 128) s_bias[t] = bias[t];
    __syncthreads();

    const int warp = t >> 5, lane = t & 31, g = lane >> 2, t4 = lane & 3;
    const int wm = (warp >> 2) * 32, wn = (warp & 3) * 32;
    const int m = t >> 2, q = t & 3;       // A loader coords
    const int n = t >> 1, half = t & 1;    // B loader coords

    // LDSM per-lane addresses
    const int rA = (lane & 7) + ((lane >> 3) & 1) * 8;
    const int cH = (lane >> 4) * 4;
    const uint32_t aH0 = smaddr(&sAh[(wm + rA) * SK + cH]);
    const uint32_t aH1 = smaddr(&sAh[(wm + 16 + rA) * SK + cH]);
    const uint32_t aL0 = smaddr(&sAl[(wm + rA) * SK + cH]);
    const uint32_t aL1 = smaddr(&sAl[(wm + 16 + rA) * SK + cH]);
    const int rB = lane & 15;
    const uint32_t bH0 = smaddr(&sBh[(wn + rB) * SK + cH]);
    const uint32_t bH1 = smaddr(&sBh[(wn + 16 + rB) * SK + cH]);
    const uint32_t bL0 = smaddr(&sBl[(wn + rB) * SK + cH]);
    const uint32_t bL1 = smaddr(&sBl[(wn + 16 + rB) * SK + cH]);

    float acc[2][4][4];
#pragma unroll
    for (int i = 0; i < 2; i++)
#pragma unroll
        for (int j = 0; j < 4; j++)
#pragma unroll
            for (int k = 0; k < 4; k++) acc[i][j][k] = 0.f;

    // prefetch chunk 0
    float4 va0, va1;
    uint4 qh0, qh1, ql0, ql1;
    {
        const float* src = x + (size_t)rowidx[m] * ND + q * 8;
        va0 = ((const float4*)src)[0]; va1 = ((const float4*)src)[1];
        const uint4* pH = (const uint4*)&g_W1T_hi[n * 64 + half * 8];
        const uint4* pL = (const uint4*)&g_W1T_lo[n * 64 + half * 8];
        qh0 = pH[0]; qh1 = pH[1]; ql0 = pL[0]; ql1 = pL[1];
    }

#pragma unroll
    for (int s = 0; s < 4; s++) {
        {   // store A chunk from regs
            uint32_t h0, l0, h1, l1, h2, l2, h3, l3;
            split2(va0.x, va0.y, h0, l0); split2(va0.z, va0.w, h1, l1);
            split2(va1.x, va1.y, h2, l2); split2(va1.z, va1.w, h3, l3);
            uint32_t* dh = &sAh[m * SK + q * 4];
            uint32_t* dl = &sAl[m * SK + q * 4];
            dh[0] = h0; dh[1] = h1; dh[2] = h2; dh[3] = h3;
            dl[0] = l0; dl[1] = l1; dl[2] = l2; dl[3] = l3;
        }
        {   // store B chunk from regs
            uint32_t* dh = &sBh[n * SK + half * 8];
            uint32_t* dl = &sBl[n * SK + half * 8];
            dh[0] = qh0.x; dh[1] = qh0.y; dh[2] = qh0.z; dh[3] = qh0.w;
            dh[4] = qh1.x; dh[5] = qh1.y; dh[6] = qh1.z; dh[7] = qh1.w;
            dl[0] = ql0.x; dl[1] = ql0.y; dl[2] = ql0.z; dl[3] = ql0.w;
            dl[4] = ql1.x; dl[5] = ql1.y; dl[6] = ql1.z; dl[7] = ql1.w;
        }
        __syncthreads();
        if (s < 3) {    // prefetch next chunk during MMA
            int kb = (s + 1) * 32 + q * 8;
            const float* src = (s + 1 < 2)
                ? (x + (size_t)rowidx[m] * ND + kb)
                : (ea + (size_t)(tile * 64 + m) * ND + (kb - 64));
            va0 = ((const float4*)src)[0]; va1 = ((const float4*)src)[1];
            const uint4* pH = (const uint4*)&g_W1T_hi[n * 64 + (s + 1) * 16 + half * 8];
            const uint4* pL = (const uint4*)&g_W1T_lo[n * 64 + (s + 1) * 16 + half * 8];
            qh0 = pH[0]; qh1 = pH[1]; ql0 = pL[0]; ql1 = pL[1];
        }
        mma_chunk_ldsm(aH0, aH1, aL0, aL1, bH0, bH1, bL0, bL1, acc);
        __syncthreads();
    }

    // epilogue: +bias, store h1, column stats
    float s8[8] = {0, 0, 0, 0, 0, 0, 0, 0}, q8[8] = {0, 0, 0, 0, 0, 0, 0, 0};
#pragma unroll
    for (int mt = 0; mt < 2; mt++) {
        int r0 = wm + mt * 16 + g;
#pragma unroll
        for (int nt = 0; nt < 4; nt++) {
            int c = wn + nt * 8 + 2 * t4;
            float bx = s_bias[c], by = s_bias[c + 1];
            float v00 = acc[mt][nt][0] + bx, v01 = acc[mt][nt][1] + by;
            float v10 = acc[mt][nt][2] + bx, v11 = acc[mt][nt][3] + by;
            size_t e0 = (size_t)(tile * 64 + r0) * H + c;
            float2 w0 = {v00, v01}, w1 = {v10, v11};
            *(float2*)&g_h1[e0] = w0;
            *(float2*)&g_h1[e0 + (size_t)8 * H] = w1;
            s8[nt * 2]     += v00 + v10;
            s8[nt * 2 + 1] += v01 + v11;
            q8[nt * 2]     += v00 * v00 + v10 * v10;
            q8[nt * 2 + 1] += v01 * v01 + v11 * v11;
        }
    }
#pragma unroll
    for (int j = 0; j < 8; j++)
#pragma unroll
        for (int o = 4; o < 32; o <<= 1) {
            s8[j] += __shfl_xor_sync(0xffffffffu, s8[j], o);
            q8[j] += __shfl_xor_sync(0xffffffffu, q8[j], o);
        }
    if (lane < 4) {
        int wr = warp >> 2;
#pragma unroll
        for (int nt = 0; nt < 4; nt++) {
            red_s[wr][wn + nt * 8 + 2 * lane]     = s8[nt * 2];
            red_s[wr][wn + nt * 8 + 2 * lane + 1] = s8[nt * 2 + 1];
            red_q[wr][wn + nt * 8 + 2 * lane]     = q8[nt * 2];
            red_q[wr][wn + nt * 8 + 2 * lane + 1] = q8[nt * 2 + 1];
        }
    }
    __syncthreads();
    if (t < 128) {
        atomicAdd(&g_sum[t],   red_s[0][t] + red_s[1][t]);
        atomicAdd(&g_sumsq[t], red_q[0][t] + red_q[1][t]);
    }
}

// ============================================================================
// Edge GEMM2 + scatter: agg[col] += relu(BN(h1)) @ W2a + b2a
// ============================================================================
__global__ __launch_bounds__(256, 2) void edge_mma2(
    const int* __restrict__ ei, const float* __restrict__ bias) {
    __shared__ uint32_t sAh[64 * SK], sAl[64 * SK];
    __shared__ uint32_t sBh[128 * SK], sBl[128 * SK];
    __shared__ int colidx[64];
    __shared__ float s_bias[128], s_sc[128], s_sh[128];

    const int t = threadIdx.x, tile = blockIdx.x;
    if (t < 64) colidx[t] = ei[NEDGES + tile * 64 + t];
    if (t < 128) { s_bias[t] = bias[t]; s_sc[t] = g_scale[t]; s_sh[t] = g_shift[t]; }
    __syncthreads();

    const int warp = t >> 5, lane = t & 31, g = lane >> 2, t4 = lane & 3;
    const int wm = (warp >> 2) * 32, wn = (warp & 3) * 32;
    const int m = t >> 2, q = t & 3;
    const int n = t >> 1, half = t & 1;

    const int rA = (lane & 7) + ((lane >> 3) & 1) * 8;
    const int cH = (lane >> 4) * 4;
    const uint32_t aH0 = smaddr(&sAh[(wm + rA) * SK + cH]);
    const uint32_t aH1 = smaddr(&sAh[(wm + 16 + rA) * SK + cH]);
    const uint32_t aL0 = smaddr(&sAl[(wm + rA) * SK + cH]);
    const uint32_t aL1 = smaddr(&sAl[(wm + 16 + rA) * SK + cH]);
    const int rB = lane & 15;
    const uint32_t bH0 = smaddr(&sBh[(wn + rB) * SK + cH]);
    const uint32_t bH1 = smaddr(&sBh[(wn + 16 + rB) * SK + cH]);
    const uint32_t bL0 = smaddr(&sBl[(wn + rB) * SK + cH]);
    const uint32_t bL1 = smaddr(&sBl[(wn + 16 + rB) * SK + cH]);

    float acc[2][4][4];
#pragma unroll
    for (int i = 0; i < 2; i++)
#pragma unroll
        for (int j = 0; j < 4; j++)
#pragma unroll
            for (int k = 0; k < 4; k++) acc[i][j][k] = 0.f;

    // prefetch chunk 0
    float4 va0, va1;
    uint4 qh0, qh1, ql0, ql1;
    {
        const float* src = g_h1 + (size_t)(tile * 64 + m) * H + q * 8;
        va0 = ((const float4*)src)[0]; va1 = ((const float4*)src)[1];
        const uint4* pH = (const uint4*)&g_W2T_hi[n * 64 + half * 8];
        const uint4* pL = (const uint4*)&g_W2T_lo[n * 64 + half * 8];
        qh0 = pH[0]; qh1 = pH[1]; ql0 = pL[0]; ql1 = pL[1];
    }

#pragma unroll
    for (int s = 0; s < 4; s++) {
        {   // BN + relu + split + store A
            int kb = s * 32 + q * 8;
            float4 v0 = va0, v1 = va1;
            v0.x = fmaxf(fmaf(v0.x, s_sc[kb],     s_sh[kb]),     0.f);
            v0.y = fmaxf(fmaf(v0.y, s_sc[kb + 1], s_sh[kb + 1]), 0.f);
            v0.z = fmaxf(fmaf(v0.z, s_sc[kb + 2], s_sh[kb + 2]), 0.f);
            v0.w = fmaxf(fmaf(v0.w, s_sc[kb + 3], s_sh[kb + 3]), 0.f);
            v1.x = fmaxf(fmaf(v1.x, s_sc[kb + 4], s_sh[kb + 4]), 0.f);
            v1.y = fmaxf(fmaf(v1.y, s_sc[kb + 5], s_sh[kb + 5]), 0.f);
            v1.z = fmaxf(fmaf(v1.z, s_sc[kb + 6], s_sh[kb + 6]), 0.f);
            v1.w = fmaxf(fmaf(v1.w, s_sc[kb + 7], s_sh[kb + 7]), 0.f);
            uint32_t h0, l0, h1, l1, h2, l2, h3, l3;
            split2(v0.x, v0.y, h0, l0); split2(v0.z, v0.w, h1, l1);
            split2(v1.x, v1.y, h2, l2); split2(v1.z, v1.w, h3, l3);
            uint32_t* dh = &sAh[m * SK + q * 4];
            uint32_t* dl = &sAl[m * SK + q * 4];
            dh[0] = h0; dh[1] = h1; dh[2] = h2; dh[3] = h3;
            dl[0] = l0; dl[1] = l1; dl[2] = l2; dl[3] = l3;
        }
        {   // store B
            uint32_t* dh = &sBh[n * SK + half * 8];
            uint32_t* dl = &sBl[n * SK + half * 8];
            dh[0] = qh0.x; dh[1] = qh0.y; dh[2] = qh0.z; dh[3] = qh0.w;
            dh[4] = qh1.x; dh[5] = qh1.y; dh[6] = qh1.z; dh[7] = qh1.w;
            dl[0] = ql0.x; dl[1] = ql0.y; dl[2] = ql0.z; dl[3] = ql0.w;
            dl[4] = ql1.x; dl[5] = ql1.y; dl[6] = ql1.z; dl[7] = ql1.w;
        }
        __syncthreads();
        if (s < 3) {
            const float* src = g_h1 + (size_t)(tile * 64 + m) * H + (s + 1) * 32 + q * 8;
            va0 = ((const float4*)src)[0]; va1 = ((const float4*)src)[1];
            const uint4* pH = (const uint4*)&g_W2T_hi[n * 64 + (s + 1) * 16 + half * 8];
            const uint4* pL = (const uint4*)&g_W2T_lo[n * 64 + (s + 1) * 16 + half * 8];
            qh0 = pH[0]; qh1 = pH[1]; ql0 = pL[0]; ql1 = pL[1];
        }
        mma_chunk_ldsm(aH0, aH1, aL0, aL1, bH0, bH1, bL0, bL1, acc);
        __syncthreads();
    }

    // epilogue: + bias, atomic scatter-add
#pragma unroll
    for (int mt = 0; mt < 2; mt++) {
        int r0 = wm + mt * 16 + g;
        int n0 = colidx[r0], n1 = colidx[r0 + 8];
#pragma unroll
        for (int nt = 0; nt < 4; nt++) {
            int c = wn + nt * 8 + 2 * t4;
            float bx = s_bias[c], by = s_bias[c + 1];
            atomicAdd(&g_agg[(size_t)n0 * H + c],     acc[mt][nt][0] + bx);
            atomicAdd(&g_agg[(size_t)n0 * H + c + 1], acc[mt][nt][1] + by);
            atomicAdd(&g_agg[(size_t)n1 * H + c],     acc[mt][nt][2] + bx);
            atomicAdd(&g_agg[(size_t)n1 * H + c + 1], acc[mt][nt][3] + by);
        }
    }
}

// ---------------- f32x2 helpers (node-side SIMT kernels, proven) -------------
__device__ __forceinline__ unsigned long long pack2(float a, float b) {
    unsigned long long r; asm("mov.b64 %0, {%1, %2};" : "=l"(r) : "f"(a), "f"(b)); return r;
}
__device__ __forceinline__ void fma2(unsigned long long& d, unsigned long long a,
                                     unsigned long long b) {
    asm("fma.rn.f32x2 %0, %1, %2, %0;" : "+l"(d) : "l"(a), "l"(b));
}
__device__ __forceinline__ float2 unpack2(unsigned long long v) {
    float2 f; asm("mov.b64 {%0, %1}, %2;" : "=f"(f.x), "=f"(f.y) : "l"(v)); return f;
}

// ============================================================================
// Node GEMM1 (SIMT, proven): h2 = concat(x, agg) @ W1b + b1b + stats
// ============================================================================
__global__ __launch_bounds__(256) void node_gemm1(
    const float* __restrict__ x, const float* __restrict__ W,
    const float* __restrict__ bias) {
    __shared__ float As[16][64];
    __shared__ float Ws[16][128];
    __shared__ float red[16][128];

    const int tid = threadIdx.x;
    const int tx = tid & 15, ty = tid >> 4;
    const int row0 = blockIdx.x * 64;

    unsigned long long acc[4][4];
#pragma unroll
    for (int i = 0; i < 4; i++)
#pragma unroll
        for (int j = 0; j < 4; j++) acc[i][j] = 0ULL;

    const int lr = tid & 63;
    const int lk4 = (tid >> 6) << 2;
    const int n_load = row0 + lr;

    for (int k0 = 0; k0 < 192; k0 += 16) {
        int kk = k0 + lk4;
        float4 v = {0.f, 0.f, 0.f, 0.f};
        if (n_load < NNODES) {
            if (kk < 64) v = *(const float4*)&x[(size_t)n_load * ND + kk];
            else         v = *(const float4*)&g_agg[(size_t)n_load * H + (kk - 64)];
        }
        As[lk4 + 0][lr] = v.x; As[lk4 + 1][lr] = v.y;
        As[lk4 + 2][lr] = v.z; As[lk4 + 3][lr] = v.w;

        int idx = tid * 8, wkr = idx >> 7, wc = idx & 127;
        *(float4*)&Ws[wkr][wc]     = *(const float4*)&W[(k0 + wkr) * H + wc];
        *(float4*)&Ws[wkr][wc + 4] = *(const float4*)&W[(k0 + wkr) * H + wc + 4];
        __syncthreads();

#pragma unroll
        for (int k = 0; k < 16; k++) {
            float4 a4 = *(const float4*)&As[k][ty * 4];
            float4 b0 = *(const float4*)&Ws[k][tx * 8];
            float4 b1 = *(const float4*)&Ws[k][tx * 8 + 4];
            unsigned long long bp[4] = {pack2(b0.x, b0.y), pack2(b0.z, b0.w),
                                        pack2(b1.x, b1.y), pack2(b1.z, b1.w)};
            float ar[4] = {a4.x, a4.y, a4.z, a4.w};
#pragma unroll
            for (int i = 0; i < 4; i++) {
                unsigned long long ap = pack2(ar[i], ar[i]);
#pragma unroll
                for (int j = 0; j < 4; j++) fma2(acc[i][j], ap, bp[j]);
            }
        }
        __syncthreads();
    }

    float2 s2[4], q2[4];
#pragma unroll
    for (int j = 0; j < 4; j++) { s2[j] = make_float2(0.f, 0.f); q2[j] = make_float2(0.f, 0.f); }
#pragma unroll
    for (int i = 0; i < 4; i++) {
        int nn = row0 + ty * 4 + i;
        if (nn >= NNODES) continue;
#pragma unroll
        for (int j = 0; j < 4; j++) {
            int c0 = tx * 8 + 2 * j;
            float2 v = unpack2(acc[i][j]);
            v.x += bias[c0]; v.y += bias[c0 + 1];
            *(float2*)&g_h2[(size_t)nn * H + c0] = v;
            s2[j].x += v.x; s2[j].y += v.y;
            q2[j].x += v.x * v.x; q2[j].y += v.y * v.y;
        }
    }
#pragma unroll
    for (int j = 0; j < 4; j++) *(float2*)&red[ty][tx * 8 + 2 * j] = s2[j];
    __syncthreads();
    if (tid < 128) {
        float s = 0.f;
#pragma unroll
        for (int tt = 0; tt < 16; tt++) s += red[tt][tid];
        atomicAdd(&g_sum[tid], s);
    }
    __syncthreads();
#pragma unroll
    for (int j = 0; j < 4; j++) *(float2*)&red[ty][tx * 8 + 2 * j] = q2[j];
    __syncthreads();
    if (tid < 128) {
        float s = 0.f;
#pragma unroll
        for (int tt = 0; tt < 16; tt++) s += red[tt][tid];
        atomicAdd(&g_sumsq[tid], s);
    }
}

// ============================================================================
// Node GEMM2 (SIMT, proven): out = relu(BN(h2)) @ W2b + b2b
// ============================================================================
__global__ __launch_bounds__(256) void node_gemm2(
    const float* __restrict__ W, const float* __restrict__ bias,
    float* __restrict__ out) {
    __shared__ float As[16][64];
    __shared__ float Ws[16][64];

    const int tid = threadIdx.x;
    const int tx = tid & 15, ty = tid >> 4;
    const int row0 = blockIdx.x * 64;

    unsigned long long acc[4][2];
#pragma unroll
    for (int i = 0; i < 4; i++) { acc[i][0] = 0ULL; acc[i][1] = 0ULL; }

    const int lr = tid & 63;
    const int lk4 = (tid >> 6) << 2;
    const int n_load = row0 + lr;

    for (int k0 = 0; k0 < 128; k0 += 16) {
        int kk = k0 + lk4;
        float4 v = {0.f, 0.f, 0.f, 0.f};
        if (n_load < NNODES) {
            v = *(const float4*)&g_h2[(size_t)n_load * H + kk];
            float4 sc = *(const float4*)&g_scale[kk];
            float4 sh = *(const float4*)&g_shift[kk];
            v.x = fmaxf(fmaf(v.x, sc.x, sh.x), 0.f);
            v.y = fmaxf(fmaf(v.y, sc.y, sh.y), 0.f);
            v.z = fmaxf(fmaf(v.z, sc.z, sh.z), 0.f);
            v.w = fmaxf(fmaf(v.w, sc.w, sh.w), 0.f);
        }
        As[lk4 + 0][lr] = v.x; As[lk4 + 1][lr] = v.y;
        As[lk4 + 2][lr] = v.z; As[lk4 + 3][lr] = v.w;

        int idx = tid * 4, wkr = idx >> 6, wc = idx & 63;
        *(float4*)&Ws[wkr][wc] = *(const float4*)&W[(k0 + wkr) * OUTD + wc];
        __syncthreads();

#pragma unroll
        for (int k = 0; k < 16; k++) {
            float4 a4 = *(const float4*)&As[k][ty * 4];
            float4 b0 = *(const float4*)&Ws[k][tx * 4];
            unsigned long long bp[2] = {pack2(b0.x, b0.y), pack2(b0.z, b0.w)};
            float ar[4] = {a4.x, a4.y, a4.z, a4.w};
#pragma unroll
            for (int i = 0; i < 4; i++) {
                unsigned long long ap = pack2(ar[i], ar[i]);
                fma2(acc[i][0], ap, bp[0]);
                fma2(acc[i][1], ap, bp[1]);
            }
        }
        __syncthreads();
    }

#pragma unroll
    for (int i = 0; i < 4; i++) {
        int nn = row0 + ty * 4 + i;
        if (nn >= NNODES) continue;
#pragma unroll
        for (int j = 0; j < 2; j++) {
            int c0 = tx * 4 + 2 * j;
            float2 v = unpack2(acc[i][j]);
            v.x += bias[c0]; v.y += bias[c0 + 1];
            *(float2*)&out[(size_t)nn * OUTD + c0] = v;
        }
    }
}

// ============================================================================
extern "C" void kernel_launch(void* const* d_in, const int* in_sizes, int n_in,
                              void* d_out, int out_size) {
    const float* x    = (const float*)d_in[0];
    const int*   ei   = (const int*)d_in[1];
    const float* ea   = (const float*)d_in[2];
    const float* W1a  = (const float*)d_in[5];
    const float* b1a  = (const float*)d_in[6];
    const float* g1a  = (const float*)d_in[7];
    const float* be1a = (const float*)d_in[8];
    const float* W2a  = (const float*)d_in[9];
    const float* b2a  = (const float*)d_in[10];
    const float* W1b  = (const float*)d_in[11];
    const float* b1b  = (const float*)d_in[12];
    const float* g1b  = (const float*)d_in[13];
    const float* be1b = (const float*)d_in[14];
    const float* W2b  = (const float*)d_in[15];
    const float* b2b  = (const float*)d_in[16];
    float* out = (float*)d_out;

    const int edge_tiles = NEDGES / 64;          // 12500
    const int node_blocks = (NNODES + 63) / 64;  // 782

    zero_kernel<<<(NNODES * H / 4 + 255) / 256, 256>>>();
    wsplit<<<32, 256>>>(W1a, 0);
    wsplit<<<32, 256>>>(W2a, 1);

    edge_mma1<<<edge_tiles, 256>>>(x, ei, ea, b1a);
    finalize_bn<<<1, 128>>>(g1a, be1a, 1.0f / (float)NEDGES);
    edge_mma2<<<edge_tiles, 256>>>(ei, b2a);
    node_gemm1<<<node_blocks, 256>>>(x, W1b, b1b);
    finalize_bn<<<1, 128>>>(g1b, be1b, 1.0f / (float)NNODES);
    node_gemm2<<<node_blocks, 256>>>(W2b, b2b, out);
}

// round 8
// speedup vs baseline: 2.7042x; 1.0360x over previous
#include <cuda_runtime.h>
#include <cuda_bf16.h>
#include <cstdint>

#define NNODES 50000
#define NEDGES 800000
#define ND     64
#define H      128
#define OUTD   64
#define BN_EPS 1e-5f
#define NTILES2 (NEDGES / 128)   // 6250 tiles of 128 edges

// ---------------- scratch (device globals; no allocations allowed) ----------
__device__ float g_h1[(size_t)NEDGES * H];     // [edge][col]
__device__ float g_agg[(size_t)NNODES * H];
__device__ float g_h2[(size_t)NNODES * H];
__device__ float g_sum[H];
__device__ float g_sumsq[H];
__device__ float g_scale[H];
__device__ float g_shift[H];
// pre-split transposed weights: word (n, kpair) = bf16{k even}|bf16{k odd}<<16
__device__ __align__(16) uint32_t g_W1T_hi[128 * 64];
__device__ __align__(16) uint32_t g_W1T_lo[128 * 64];
__device__ __align__(16) uint32_t g_W2T_hi[128 * 64];
__device__ __align__(16) uint32_t g_W2T_lo[128 * 64];

// ---------------- helpers ----------------------------------------------------
__device__ __forceinline__ void split2(float a, float b, uint32_t& hi, uint32_t& lo) {
    __nv_bfloat16 ah = __float2bfloat16_rn(a), bh = __float2bfloat16_rn(b);
    float ar = a - __bfloat162float(ah);
    float br = b - __bfloat162float(bh);
    __nv_bfloat16 al = __float2bfloat16_rn(ar), bl = __float2bfloat16_rn(br);
    hi = (uint32_t)__bfloat16_as_ushort(ah) | ((uint32_t)__bfloat16_as_ushort(bh) << 16);
    lo = (uint32_t)__bfloat16_as_ushort(al) | ((uint32_t)__bfloat16_as_ushort(bl) << 16);
}

__device__ __forceinline__ void mma4(float* c, const uint32_t* a, uint32_t b0, uint32_t b1) {
    asm volatile(
        "mma.sync.aligned.m16n8k16.row.col.f32.bf16.bf16.f32 "
        "{%0,%1,%2,%3}, {%4,%5,%6,%7}, {%8,%9}, {%0,%1,%2,%3};"
        : "+f"(c[0]), "+f"(c[1]), "+f"(c[2]), "+f"(c[3])
        : "r"(a[0]), "r"(a[1]), "r"(a[2]), "r"(a[3]), "r"(b0), "r"(b1));
}

__device__ __forceinline__ void ldsm4(uint32_t* r, uint32_t addr) {
    asm volatile("ldmatrix.sync.aligned.m8n8.x4.shared.b16 {%0,%1,%2,%3}, [%4];"
                 : "=r"(r[0]), "=r"(r[1]), "=r"(r[2]), "=r"(r[3]) : "r"(addr));
}

__device__ __forceinline__ uint32_t smaddr(const void* p) {
    return (uint32_t)__cvta_generic_to_shared(p);
}

#define SK 20    // smem stride words (16 kpairs + 4 pad); LDSM-conflict-free

// One k32 chunk of bf16x3 MMA via ldmatrix feeds (proven round-6 routine).
__device__ __forceinline__ void mma_chunk_ldsm(
    uint32_t aH0, uint32_t aH1, uint32_t aL0, uint32_t aL1,
    uint32_t bH0, uint32_t bH1, uint32_t bL0, uint32_t bL1,
    float acc[2][4][4]) {
#pragma unroll
    for (int kc = 0; kc < 2; kc++) {
        const uint32_t kb = kc * 32;
        uint32_t a0[4], a1[4], b0[4], b1[4];
        ldsm4(a0, aH0 + kb); ldsm4(a1, aH1 + kb);
        ldsm4(b0, bH0 + kb); ldsm4(b1, bH1 + kb);
        mma4(acc[0][0], a0, b0[0], b0[2]); mma4(acc[0][1], a0, b0[1], b0[3]);
        mma4(acc[0][2], a0, b1[0], b1[2]); mma4(acc[0][3], a0, b1[1], b1[3]);
        mma4(acc[1][0], a1, b0[0], b0[2]); mma4(acc[1][1], a1, b0[1], b0[3]);
        mma4(acc[1][2], a1, b1[0], b1[2]); mma4(acc[1][3], a1, b1[1], b1[3]);
        uint32_t c0[4], c1[4];
        ldsm4(c0, bL0 + kb); ldsm4(c1, bL1 + kb);
        mma4(acc[0][0], a0, c0[0], c0[2]); mma4(acc[0][1], a0, c0[1], c0[3]);
        mma4(acc[0][2], a0, c1[0], c1[2]); mma4(acc[0][3], a0, c1[1], c1[3]);
        mma4(acc[1][0], a1, c0[0], c0[2]); mma4(acc[1][1], a1, c0[1], c0[3]);
        mma4(acc[1][2], a1, c1[0], c1[2]); mma4(acc[1][3], a1, c1[1], c1[3]);
        uint32_t d0[4], d1[4];
        ldsm4(d0, aL0 + kb); ldsm4(d1, aL1 + kb);
        mma4(acc[0][0], d0, b0[0], b0[2]); mma4(acc[0][1], d0, b0[1], b0[3]);
        mma4(acc[0][2], d0, b1[0], b1[2]); mma4(acc[0][3], d0, b1[1], b1[3]);
        mma4(acc[1][0], d1, b0[0], b0[2]); mma4(acc[1][1], d1, b0[1], b0[3]);
        mma4(acc[1][2], d1, b1[0], b1[2]); mma4(acc[1][3], d1, b1[1], b1[3]);
    }
}

// ---------------- small kernels ----------------------------------------------
__global__ void zero_kernel() {
    int i = blockIdx.x * blockDim.x + threadIdx.x;
    const float4 z = {0.f, 0.f, 0.f, 0.f};
    if (i < NNODES * H / 4) ((float4*)g_agg)[i] = z;
    if (i < H / 4) { ((float4*)g_sum)[i] = z; ((float4*)g_sumsq)[i] = z; }
}

__global__ void finalize_bn(const float* __restrict__ gamma,
                            const float* __restrict__ beta, float invM) {
    int c = threadIdx.x;
    float mean = g_sum[c] * invM;
    float var  = g_sumsq[c] * invM - mean * mean;
    float sc   = gamma[c] * rsqrtf(var + BN_EPS);
    g_scale[c] = sc;
    g_shift[c] = beta[c] - mean * sc;
    g_sum[c] = 0.f; g_sumsq[c] = 0.f;
}

__global__ void wsplit(const float* __restrict__ W, int which) {
    uint32_t* hi = (which == 0) ? g_W1T_hi : g_W2T_hi;
    uint32_t* lo = (which == 0) ? g_W1T_lo : g_W2T_lo;
    int i = blockIdx.x * 256 + threadIdx.x;
    if (i >= 128 * 64) return;
    int n = i >> 6, kp = i & 63;
    float a = W[(2 * kp) * 128 + n];
    float b = W[(2 * kp + 1) * 128 + n];
    uint32_t h, l;
    split2(a, b, h, l);
    hi[i] = h; lo[i] = l;
}

// ============================================================================
// Edge GEMM1: h1 = concat(x[row], ea) @ W1a + b1a ; fused BN stats.
// 128(M) x 128(N) tile, 512 threads (16 warps of proven 32x32 warp tile).
// Static smem: 40KB tiles + ~4KB misc.
// ============================================================================
__global__ __launch_bounds__(512, 1) void edge_mma1(
    const float* __restrict__ x, const int* __restrict__ ei,
    const float* __restrict__ ea, const float* __restrict__ bias) {
    __shared__ uint32_t sAh[128 * SK], sAl[128 * SK];
    __shared__ uint32_t sBh[128 * SK], sBl[128 * SK];
    __shared__ int rowidx[128];
    __shared__ float s_bias[128];
    __shared__ float red_s[4][128], red_q[4][128];

    const int t = threadIdx.x, tile = blockIdx.x;
    if (t < 128) { rowidx[t] = ei[tile * 128 + t]; s_bias[t] = bias[t]; }
    __syncthreads();

    const int warp = t >> 5, lane = t & 31, g = lane >> 2, t4 = lane & 3;
    const int wm = (warp >> 2) * 32, wn = (warp & 3) * 32;
    const int m = t >> 2, q = t & 3;     // A loader: row m (0..127), k-quarter q
    const int n = t >> 2, qb = t & 3;    // B loader: row n (0..127), kpair quarter

    // LDSM per-lane addresses (proven mapping)
    const int rA = (lane & 7) + ((lane >> 3) & 1) * 8;
    const int cH = (lane >> 4) * 4;
    const uint32_t aH0 = smaddr(&sAh[(wm + rA) * SK + cH]);
    const uint32_t aH1 = smaddr(&sAh[(wm + 16 + rA) * SK + cH]);
    const uint32_t aL0 = smaddr(&sAl[(wm + rA) * SK + cH]);
    const uint32_t aL1 = smaddr(&sAl[(wm + 16 + rA) * SK + cH]);
    const int rB = lane & 15;
    const uint32_t bH0 = smaddr(&sBh[(wn + rB) * SK + cH]);
    const uint32_t bH1 = smaddr(&sBh[(wn + 16 + rB) * SK + cH]);
    const uint32_t bL0 = smaddr(&sBl[(wn + rB) * SK + cH]);
    const uint32_t bL1 = smaddr(&sBl[(wn + 16 + rB) * SK + cH]);

    float acc[2][4][4];
#pragma unroll
    for (int i = 0; i < 2; i++)
#pragma unroll
        for (int j = 0; j < 4; j++)
#pragma unroll
            for (int k = 0; k < 4; k++) acc[i][j][k] = 0.f;

    // prefetch chunk 0
    float4 va0, va1;
    uint4 qh, ql;
    {
        const float* src = x + (size_t)rowidx[m] * ND + q * 8;
        va0 = ((const float4*)src)[0]; va1 = ((const float4*)src)[1];
        qh = *(const uint4*)&g_W1T_hi[n * 64 + qb * 4];
        ql = *(const uint4*)&g_W1T_lo[n * 64 + qb * 4];
    }

#pragma unroll
    for (int s = 0; s < 4; s++) {
        {   // store A chunk from regs (split on the fly)
            uint32_t h0, l0, h1, l1, h2, l2, h3, l3;
            split2(va0.x, va0.y, h0, l0); split2(va0.z, va0.w, h1, l1);
            split2(va1.x, va1.y, h2, l2); split2(va1.z, va1.w, h3, l3);
            *(uint4*)&sAh[m * SK + q * 4] = make_uint4(h0, h1, h2, h3);
            *(uint4*)&sAl[m * SK + q * 4] = make_uint4(l0, l1, l2, l3);
        }
        {   // store B chunk from regs
            *(uint4*)&sBh[n * SK + qb * 4] = qh;
            *(uint4*)&sBl[n * SK + qb * 4] = ql;
        }
        __syncthreads();
        if (s < 3) {    // prefetch next chunk during MMA
            int kb = (s + 1) * 32 + q * 8;
            const float* src = (s + 1 < 2)
                ? (x + (size_t)rowidx[m] * ND + kb)
                : (ea + (size_t)(tile * 128 + m) * ND + (kb - 64));
            va0 = ((const float4*)src)[0]; va1 = ((const float4*)src)[1];
            qh = *(const uint4*)&g_W1T_hi[n * 64 + (s + 1) * 16 + qb * 4];
            ql = *(const uint4*)&g_W1T_lo[n * 64 + (s + 1) * 16 + qb * 4];
        }
        mma_chunk_ldsm(aH0, aH1, aL0, aL1, bH0, bH1, bL0, bL1, acc);
        __syncthreads();
    }

    // epilogue: +bias, store h1, column stats
    float s8[8] = {0, 0, 0, 0, 0, 0, 0, 0}, q8[8] = {0, 0, 0, 0, 0, 0, 0, 0};
#pragma unroll
    for (int mt = 0; mt < 2; mt++) {
        int r0 = wm + mt * 16 + g;
#pragma unroll
        for (int nt = 0; nt < 4; nt++) {
            int c = wn + nt * 8 + 2 * t4;
            float bx = s_bias[c], by = s_bias[c + 1];
            float v00 = acc[mt][nt][0] + bx, v01 = acc[mt][nt][1] + by;
            float v10 = acc[mt][nt][2] + bx, v11 = acc[mt][nt][3] + by;
            size_t e0 = (size_t)(tile * 128 + r0) * H + c;
            float2 w0 = {v00, v01}, w1 = {v10, v11};
            *(float2*)&g_h1[e0] = w0;
            *(float2*)&g_h1[e0 + (size_t)8 * H] = w1;
            s8[nt * 2]     += v00 + v10;
            s8[nt * 2 + 1] += v01 + v11;
            q8[nt * 2]     += v00 * v00 + v10 * v10;
            q8[nt * 2 + 1] += v01 * v01 + v11 * v11;
        }
    }
#pragma unroll
    for (int j = 0; j < 8; j++)
#pragma unroll
        for (int o = 4; o < 32; o <<= 1) {
            s8[j] += __shfl_xor_sync(0xffffffffu, s8[j], o);
            q8[j] += __shfl_xor_sync(0xffffffffu, q8[j], o);
        }
    if (lane < 4) {
        int wr = warp >> 2;   // row-group; same-wr warps write disjoint wn ranges
#pragma unroll
        for (int nt = 0; nt < 4; nt++) {
            red_s[wr][wn + nt * 8 + 2 * lane]     = s8[nt * 2];
            red_s[wr][wn + nt * 8 + 2 * lane + 1] = s8[nt * 2 + 1];
            red_q[wr][wn + nt * 8 + 2 * lane]     = q8[nt * 2];
            red_q[wr][wn + nt * 8 + 2 * lane + 1] = q8[nt * 2 + 1];
        }
    }
    __syncthreads();
    if (t < 128) {
        atomicAdd(&g_sum[t],   red_s[0][t] + red_s[1][t] + red_s[2][t] + red_s[3][t]);
        atomicAdd(&g_sumsq[t], red_q[0][t] + red_q[1][t] + red_q[2][t] + red_q[3][t]);
    }
}

// ============================================================================
// Edge GEMM2 + scatter: agg[col] += relu(BN(h1)) @ W2a + b2a   (128-edge tile)
// ============================================================================
__global__ __launch_bounds__(512, 1) void edge_mma2(
    const int* __restrict__ ei, const float* __restrict__ bias) {
    __shared__ uint32_t sAh[128 * SK], sAl[128 * SK];
    __shared__ uint32_t sBh[128 * SK], sBl[128 * SK];
    __shared__ int colidx[128];
    __shared__ float s_bias[128], s_sc[128], s_sh[128];

    const int t = threadIdx.x, tile = blockIdx.x;
    if (t < 128) {
        colidx[t] = ei[NEDGES + tile * 128 + t];
        s_bias[t] = bias[t];
        s_sc[t] = g_scale[t];
        s_sh[t] = g_shift[t];
    }
    __syncthreads();

    const int warp = t >> 5, lane = t & 31, g = lane >> 2, t4 = lane & 3;
    const int wm = (warp >> 2) * 32, wn = (warp & 3) * 32;
    const int m = t >> 2, q = t & 3;
    const int n = t >> 2, qb = t & 3;

    const int rA = (lane & 7) + ((lane >> 3) & 1) * 8;
    const int cH = (lane >> 4) * 4;
    const uint32_t aH0 = smaddr(&sAh[(wm + rA) * SK + cH]);
    const uint32_t aH1 = smaddr(&sAh[(wm + 16 + rA) * SK + cH]);
    const uint32_t aL0 = smaddr(&sAl[(wm + rA) * SK + cH]);
    const uint32_t aL1 = smaddr(&sAl[(wm + 16 + rA) * SK + cH]);
    const int rB = lane & 15;
    const uint32_t bH0 = smaddr(&sBh[(wn + rB) * SK + cH]);
    const uint32_t bH1 = smaddr(&sBh[(wn + 16 + rB) * SK + cH]);
    const uint32_t bL0 = smaddr(&sBl[(wn + rB) * SK + cH]);
    const uint32_t bL1 = smaddr(&sBl[(wn + 16 + rB) * SK + cH]);

    float acc[2][4][4];
#pragma unroll
    for (int i = 0; i < 2; i++)
#pragma unroll
        for (int j = 0; j < 4; j++)
#pragma unroll
            for (int k = 0; k < 4; k++) acc[i][j][k] = 0.f;

    // prefetch chunk 0
    float4 va0, va1;
    uint4 qh, ql;
    {
        const float* src = g_h1 + (size_t)(tile * 128 + m) * H + q * 8;
        va0 = ((const float4*)src)[0]; va1 = ((const float4*)src)[1];
        qh = *(const uint4*)&g_W2T_hi[n * 64 + qb * 4];
        ql = *(const uint4*)&g_W2T_lo[n * 64 + qb * 4];
    }

#pragma unroll
    for (int s = 0; s < 4; s++) {
        {   // BN + relu + split + store A
            int kb = s * 32 + q * 8;
            float4 v0 = va0, v1 = va1;
            v0.x = fmaxf(fmaf(v0.x, s_sc[kb],     s_sh[kb]),     0.f);
            v0.y = fmaxf(fmaf(v0.y, s_sc[kb + 1], s_sh[kb + 1]), 0.f);
            v0.z = fmaxf(fmaf(v0.z, s_sc[kb + 2], s_sh[kb + 2]), 0.f);
            v0.w = fmaxf(fmaf(v0.w, s_sc[kb + 3], s_sh[kb + 3]), 0.f);
            v1.x = fmaxf(fmaf(v1.x, s_sc[kb + 4], s_sh[kb + 4]), 0.f);
            v1.y = fmaxf(fmaf(v1.y, s_sc[kb + 5], s_sh[kb + 5]), 0.f);
            v1.z = fmaxf(fmaf(v1.z, s_sc[kb + 6], s_sh[kb + 6]), 0.f);
            v1.w = fmaxf(fmaf(v1.w, s_sc[kb + 7], s_sh[kb + 7]), 0.f);
            uint32_t h0, l0, h1, l1, h2, l2, h3, l3;
            split2(v0.x, v0.y, h0, l0); split2(v0.z, v0.w, h1, l1);
            split2(v1.x, v1.y, h2, l2); split2(v1.z, v1.w, h3, l3);
            *(uint4*)&sAh[m * SK + q * 4] = make_uint4(h0, h1, h2, h3);
            *(uint4*)&sAl[m * SK + q * 4] = make_uint4(l0, l1, l2, l3);
        }
        {   // store B
            *(uint4*)&sBh[n * SK + qb * 4] = qh;
            *(uint4*)&sBl[n * SK + qb * 4] = ql;
        }
        __syncthreads();
        if (s < 3) {
            const float* src = g_h1 + (size_t)(tile * 128 + m) * H + (s + 1) * 32 + q * 8;
            va0 = ((const float4*)src)[0]; va1 = ((const float4*)src)[1];
            qh = *(const uint4*)&g_W2T_hi[n * 64 + (s + 1) * 16 + qb * 4];
            ql = *(const uint4*)&g_W2T_lo[n * 64 + (s + 1) * 16 + qb * 4];
        }
        mma_chunk_ldsm(aH0, aH1, aL0, aL1, bH0, bH1, bL0, bL1, acc);
        __syncthreads();
    }

    // epilogue: + bias, atomic scatter-add
#pragma unroll
    for (int mt = 0; mt < 2; mt++) {
        int r0 = wm + mt * 16 + g;
        int n0 = colidx[r0], n1 = colidx[r0 + 8];
#pragma unroll
        for (int nt = 0; nt < 4; nt++) {
            int c = wn + nt * 8 + 2 * t4;
            float bx = s_bias[c], by = s_bias[c + 1];
            atomicAdd(&g_agg[(size_t)n0 * H + c],     acc[mt][nt][0] + bx);
            atomicAdd(&g_agg[(size_t)n0 * H + c + 1], acc[mt][nt][1] + by);
            atomicAdd(&g_agg[(size_t)n1 * H + c],     acc[mt][nt][2] + bx);
            atomicAdd(&g_agg[(size_t)n1 * H + c + 1], acc[mt][nt][3] + by);
        }
    }
}

// ---------------- f32x2 helpers (node-side SIMT kernels, proven) -------------
__device__ __forceinline__ unsigned long long pack2(float a, float b) {
    unsigned long long r; asm("mov.b64 %0, {%1, %2};" : "=l"(r) : "f"(a), "f"(b)); return r;
}
__device__ __forceinline__ void fma2(unsigned long long& d, unsigned long long a,
                                     unsigned long long b) {
    asm("fma.rn.f32x2 %0, %1, %2, %0;" : "+l"(d) : "l"(a), "l"(b));
}
__device__ __forceinline__ float2 unpack2(unsigned long long v) {
    float2 f; asm("mov.b64 {%0, %1}, %2;" : "=f"(f.x), "=f"(f.y) : "l"(v)); return f;
}

// ============================================================================
// Node GEMM1 (SIMT, proven): h2 = concat(x, agg) @ W1b + b1b + stats
// ============================================================================
__global__ __launch_bounds__(256) void node_gemm1(
    const float* __restrict__ x, const float* __restrict__ W,
    const float* __restrict__ bias) {
    __shared__ float As[16][64];
    __shared__ float Ws[16][128];
    __shared__ float red[16][128];

    const int tid = threadIdx.x;
    const int tx = tid & 15, ty = tid >> 4;
    const int row0 = blockIdx.x * 64;

    unsigned long long acc[4][4];
#pragma unroll
    for (int i = 0; i < 4; i++)
#pragma unroll
        for (int j = 0; j < 4; j++) acc[i][j] = 0ULL;

    const int lr = tid & 63;
    const int lk4 = (tid >> 6) << 2;
    const int n_load = row0 + lr;

    for (int k0 = 0; k0 < 192; k0 += 16) {
        int kk = k0 + lk4;
        float4 v = {0.f, 0.f, 0.f, 0.f};
        if (n_load < NNODES) {
            if (kk < 64) v = *(const float4*)&x[(size_t)n_load * ND + kk];
            else         v = *(const float4*)&g_agg[(size_t)n_load * H + (kk - 64)];
        }
        As[lk4 + 0][lr] = v.x; As[lk4 + 1][lr] = v.y;
        As[lk4 + 2][lr] = v.z; As[lk4 + 3][lr] = v.w;

        int idx = tid * 8, wkr = idx >> 7, wc = idx & 127;
        *(float4*)&Ws[wkr][wc]     = *(const float4*)&W[(k0 + wkr) * H + wc];
        *(float4*)&Ws[wkr][wc + 4] = *(const float4*)&W[(k0 + wkr) * H + wc + 4];
        __syncthreads();

#pragma unroll
        for (int k = 0; k < 16; k++) {
            float4 a4 = *(const float4*)&As[k][ty * 4];
            float4 b0 = *(const float4*)&Ws[k][tx * 8];
            float4 b1 = *(const float4*)&Ws[k][tx * 8 + 4];
            unsigned long long bp[4] = {pack2(b0.x, b0.y), pack2(b0.z, b0.w),
                                        pack2(b1.x, b1.y), pack2(b1.z, b1.w)};
            float ar[4] = {a4.x, a4.y, a4.z, a4.w};
#pragma unroll
            for (int i = 0; i < 4; i++) {
                unsigned long long ap = pack2(ar[i], ar[i]);
#pragma unroll
                for (int j = 0; j < 4; j++) fma2(acc[i][j], ap, bp[j]);
            }
        }
        __syncthreads();
    }

    float2 s2[4], q2[4];
#pragma unroll
    for (int j = 0; j < 4; j++) { s2[j] = make_float2(0.f, 0.f); q2[j] = make_float2(0.f, 0.f); }
#pragma unroll
    for (int i = 0; i < 4; i++) {
        int nn = row0 + ty * 4 + i;
        if (nn >= NNODES) continue;
#pragma unroll
        for (int j = 0; j < 4; j++) {
            int c0 = tx * 8 + 2 * j;
            float2 v = unpack2(acc[i][j]);
            v.x += bias[c0]; v.y += bias[c0 + 1];
            *(float2*)&g_h2[(size_t)nn * H + c0] = v;
            s2[j].x += v.x; s2[j].y += v.y;
            q2[j].x += v.x * v.x; q2[j].y += v.y * v.y;
        }
    }
#pragma unroll
    for (int j = 0; j < 4; j++) *(float2*)&red[ty][tx * 8 + 2 * j] = s2[j];
    __syncthreads();
    if (tid < 128) {
        float s = 0.f;
#pragma unroll
        for (int tt = 0; tt < 16; tt++) s += red[tt][tid];
        atomicAdd(&g_sum[tid], s);
    }
    __syncthreads();
#pragma unroll
    for (int j = 0; j < 4; j++) *(float2*)&red[ty][tx * 8 + 2 * j] = q2[j];
    __syncthreads();
    if (tid < 128) {
        float s = 0.f;
#pragma unroll
        for (int tt = 0; tt < 16; tt++) s += red[tt][tid];
        atomicAdd(&g_sumsq[tid], s);
    }
}

// ============================================================================
// Node GEMM2 (SIMT, proven): out = relu(BN(h2)) @ W2b + b2b
// ============================================================================
__global__ __launch_bounds__(256) void node_gemm2(
    const float* __restrict__ W, const float* __restrict__ bias,
    float* __restrict__ out) {
    __shared__ float As[16][64];
    __shared__ float Ws[16][64];

    const int tid = threadIdx.x;
    const int tx = tid & 15, ty = tid >> 4;
    const int row0 = blockIdx.x * 64;

    unsigned long long acc[4][2];
#pragma unroll
    for (int i = 0; i < 4; i++) { acc[i][0] = 0ULL; acc[i][1] = 0ULL; }

    const int lr = tid & 63;
    const int lk4 = (tid >> 6) << 2;
    const int n_load = row0 + lr;

    for (int k0 = 0; k0 < 128; k0 += 16) {
        int kk = k0 + lk4;
        float4 v = {0.f, 0.f, 0.f, 0.f};
        if (n_load < NNODES) {
            v = *(const float4*)&g_h2[(size_t)n_load * H + kk];
            float4 sc = *(const float4*)&g_scale[kk];
            float4 sh = *(const float4*)&g_shift[kk];
            v.x = fmaxf(fmaf(v.x, sc.x, sh.x), 0.f);
            v.y = fmaxf(fmaf(v.y, sc.y, sh.y), 0.f);
            v.z = fmaxf(fmaf(v.z, sc.z, sh.z), 0.f);
            v.w = fmaxf(fmaf(v.w, sc.w, sh.w), 0.f);
        }
        As[lk4 + 0][lr] = v.x; As[lk4 + 1][lr] = v.y;
        As[lk4 + 2][lr] = v.z; As[lk4 + 3][lr] = v.w;

        int idx = tid * 4, wkr = idx >> 6, wc = idx & 63;
        *(float4*)&Ws[wkr][wc] = *(const float4*)&W[(k0 + wkr) * OUTD + wc];
        __syncthreads();

#pragma unroll
        for (int k = 0; k < 16; k++) {
            float4 a4 = *(const float4*)&As[k][ty * 4];
            float4 b0 = *(const float4*)&Ws[k][tx * 4];
            unsigned long long bp[2] = {pack2(b0.x, b0.y), pack2(b0.z, b0.w)};
            float ar[4] = {a4.x, a4.y, a4.z, a4.w};
#pragma unroll
            for (int i = 0; i < 4; i++) {
                unsigned long long ap = pack2(ar[i], ar[i]);
                fma2(acc[i][0], ap, bp[0]);
                fma2(acc[i][1], ap, bp[1]);
            }
        }
        __syncthreads();
    }

#pragma unroll
    for (int i = 0; i < 4; i++) {
        int nn = row0 + ty * 4 + i;
        if (nn >= NNODES) continue;
#pragma unroll
        for (int j = 0; j < 2; j++) {
            int c0 = tx * 4 + 2 * j;
            float2 v = unpack2(acc[i][j]);
            v.x += bias[c0]; v.y += bias[c0 + 1];
            *(float2*)&out[(size_t)nn * OUTD + c0] = v;
        }
    }
}

// ============================================================================
extern "C" void kernel_launch(void* const* d_in, const int* in_sizes, int n_in,
                              void* d_out, int out_size) {
    const float* x    = (const float*)d_in[0];
    const int*   ei   = (const int*)d_in[1];
    const float* ea   = (const float*)d_in[2];
    const float* W1a  = (const float*)d_in[5];
    const float* b1a  = (const float*)d_in[6];
    const float* g1a  = (const float*)d_in[7];
    const float* be1a = (const float*)d_in[8];
    const float* W2a  = (const float*)d_in[9];
    const float* b2a  = (const float*)d_in[10];
    const float* W1b  = (const float*)d_in[11];
    const float* b1b  = (const float*)d_in[12];
    const float* g1b  = (const float*)d_in[13];
    const float* be1b = (const float*)d_in[14];
    const float* W2b  = (const float*)d_in[15];
    const float* b2b  = (const float*)d_in[16];
    float* out = (float*)d_out;

    const int node_blocks = (NNODES + 63) / 64;  // 782

    zero_kernel<<<(NNODES * H / 4 + 255) / 256, 256>>>();
    wsplit<<<32, 256>>>(W1a, 0);
    wsplit<<<32, 256>>>(W2a, 1);

    edge_mma1<<<NTILES2, 512>>>(x, ei, ea, b1a);
    finalize_bn<<<1, 128>>>(g1a, be1a, 1.0f / (float)NEDGES);
    edge_mma2<<<NTILES2, 512>>>(ei, b2a);
    node_gemm1<<<node_blocks, 256>>>(x, W1b, b1b);
    finalize_bn<<<1, 128>>>(g1b, be1b, 1.0f / (float)NNODES);
    node_gemm2<<<node_blocks, 256>>>(W2b, b2b, out);
}

// round 9
// speedup vs baseline: 2.7171x; 1.0048x over previous
#include <cuda_runtime.h>
#include <cuda_bf16.h>
#include <cstdint>

#define NNODES 50000
#define NEDGES 800000
#define ND     64
#define H      128
#define OUTD   64
#define BN_EPS 1e-5f
#define NTILES2 (NEDGES / 128)   // 6250 tiles of 128 edges

// ---------------- scratch (device globals; no allocations allowed) ----------
__device__ float g_h1[(size_t)NEDGES * H];     // [edge][col]
__device__ float g_agg[(size_t)NNODES * H];
__device__ float g_h2[(size_t)NNODES * H];
__device__ float g_sum[H];
__device__ float g_sumsq[H];
__device__ float g_scale[H];
__device__ float g_shift[H];
// pre-split transposed weights: word (n, kpair) = bf16{k even}|bf16{k odd}<<16
__device__ __align__(16) uint32_t g_W1T_hi[128 * 64];
__device__ __align__(16) uint32_t g_W1T_lo[128 * 64];
__device__ __align__(16) uint32_t g_W2T_hi[128 * 64];
__device__ __align__(16) uint32_t g_W2T_lo[128 * 64];

// ---------------- helpers ----------------------------------------------------
__device__ __forceinline__ void split2(float a, float b, uint32_t& hi, uint32_t& lo) {
    __nv_bfloat16 ah = __float2bfloat16_rn(a), bh = __float2bfloat16_rn(b);
    float ar = a - __bfloat162float(ah);
    float br = b - __bfloat162float(bh);
    __nv_bfloat16 al = __float2bfloat16_rn(ar), bl = __float2bfloat16_rn(br);
    hi = (uint32_t)__bfloat16_as_ushort(ah) | ((uint32_t)__bfloat16_as_ushort(bh) << 16);
    lo = (uint32_t)__bfloat16_as_ushort(al) | ((uint32_t)__bfloat16_as_ushort(bl) << 16);
}

__device__ __forceinline__ void mma4(float* c, const uint32_t* a, uint32_t b0, uint32_t b1) {
    asm volatile(
        "mma.sync.aligned.m16n8k16.row.col.f32.bf16.bf16.f32 "
        "{%0,%1,%2,%3}, {%4,%5,%6,%7}, {%8,%9}, {%0,%1,%2,%3};"
        : "+f"(c[0]), "+f"(c[1]), "+f"(c[2]), "+f"(c[3])
        : "r"(a[0]), "r"(a[1]), "r"(a[2]), "r"(a[3]), "r"(b0), "r"(b1));
}

__device__ __forceinline__ void ldsm4(uint32_t* r, uint32_t addr) {
    asm volatile("ldmatrix.sync.aligned.m8n8.x4.shared.b16 {%0,%1,%2,%3}, [%4];"
                 : "=r"(r[0]), "=r"(r[1]), "=r"(r[2]), "=r"(r[3]) : "r"(addr));
}

__device__ __forceinline__ uint32_t smaddr(const void* p) {
    return (uint32_t)__cvta_generic_to_shared(p);
}

__device__ __forceinline__ void red_add_v4(float* p, float a, float b, float c, float d) {
    asm volatile("red.global.add.v4.f32 [%0], {%1,%2,%3,%4};"
                 :: "l"(p), "f"(a), "f"(b), "f"(c), "f"(d) : "memory");
}

#define SK 20    // smem stride words (16 kpairs + 4 pad); LDSM-conflict-free

// One k32 chunk of bf16x3 MMA via ldmatrix feeds (proven routine).
__device__ __forceinline__ void mma_chunk_ldsm(
    uint32_t aH0, uint32_t aH1, uint32_t aL0, uint32_t aL1,
    uint32_t bH0, uint32_t bH1, uint32_t bL0, uint32_t bL1,
    float acc[2][4][4]) {
#pragma unroll
    for (int kc = 0; kc < 2; kc++) {
        const uint32_t kb = kc * 32;
        uint32_t a0[4], a1[4], b0[4], b1[4];
        ldsm4(a0, aH0 + kb); ldsm4(a1, aH1 + kb);
        ldsm4(b0, bH0 + kb); ldsm4(b1, bH1 + kb);
        mma4(acc[0][0], a0, b0[0], b0[2]); mma4(acc[0][1], a0, b0[1], b0[3]);
        mma4(acc[0][2], a0, b1[0], b1[2]); mma4(acc[0][3], a0, b1[1], b1[3]);
        mma4(acc[1][0], a1, b0[0], b0[2]); mma4(acc[1][1], a1, b0[1], b0[3]);
        mma4(acc[1][2], a1, b1[0], b1[2]); mma4(acc[1][3], a1, b1[1], b1[3]);
        uint32_t c0[4], c1[4];
        ldsm4(c0, bL0 + kb); ldsm4(c1, bL1 + kb);
        mma4(acc[0][0], a0, c0[0], c0[2]); mma4(acc[0][1], a0, c0[1], c0[3]);
        mma4(acc[0][2], a0, c1[0], c1[2]); mma4(acc[0][3], a0, c1[1], c1[3]);
        mma4(acc[1][0], a1, c0[0], c0[2]); mma4(acc[1][1], a1, c0[1], c0[3]);
        mma4(acc[1][2], a1, c1[0], c1[2]); mma4(acc[1][3], a1, c1[1], c1[3]);
        uint32_t d0[4], d1[4];
        ldsm4(d0, aL0 + kb); ldsm4(d1, aL1 + kb);
        mma4(acc[0][0], d0, b0[0], b0[2]); mma4(acc[0][1], d0, b0[1], b0[3]);
        mma4(acc[0][2], d0, b1[0], b1[2]); mma4(acc[0][3], d0, b1[1], b1[3]);
        mma4(acc[1][0], d1, b0[0], b0[2]); mma4(acc[1][1], d1, b0[1], b0[3]);
        mma4(acc[1][2], d1, b1[0], b1[2]); mma4(acc[1][3], d1, b1[1], b1[3]);
    }
}

// ---------------- small kernels ----------------------------------------------
__global__ void zero_kernel() {
    int i = blockIdx.x * blockDim.x + threadIdx.x;
    const float4 z = {0.f, 0.f, 0.f, 0.f};
    if (i < NNODES * H / 4) ((float4*)g_agg)[i] = z;
    if (i < H / 4) { ((float4*)g_sum)[i] = z; ((float4*)g_sumsq)[i] = z; }
}

__global__ void finalize_bn(const float* __restrict__ gamma,
                            const float* __restrict__ beta, float invM) {
    int c = threadIdx.x;
    float mean = g_sum[c] * invM;
    float var  = g_sumsq[c] * invM - mean * mean;
    float sc   = gamma[c] * rsqrtf(var + BN_EPS);
    g_scale[c] = sc;
    g_shift[c] = beta[c] - mean * sc;
    g_sum[c] = 0.f; g_sumsq[c] = 0.f;
}

__global__ void wsplit(const float* __restrict__ W, int which) {
    uint32_t* hi = (which == 0) ? g_W1T_hi : g_W2T_hi;
    uint32_t* lo = (which == 0) ? g_W1T_lo : g_W2T_lo;
    int i = blockIdx.x * 256 + threadIdx.x;
    if (i >= 128 * 64) return;
    int n = i >> 6, kp = i & 63;
    float a = W[(2 * kp) * 128 + n];
    float b = W[(2 * kp + 1) * 128 + n];
    uint32_t h, l;
    split2(a, b, h, l);
    hi[i] = h; lo[i] = l;
}

// ============================================================================
// Edge GEMM1: h1 = concat(x[row], ea) @ W1a + b1a ; fused BN stats.
// 128(M) x 128(N) tile, 512 threads; STG.128 epilogue via lane-pair shuffle.
// ============================================================================
__global__ __launch_bounds__(512, 1) void edge_mma1(
    const float* __restrict__ x, const int* __restrict__ ei,
    const float* __restrict__ ea, const float* __restrict__ bias) {
    __shared__ uint32_t sAh[128 * SK], sAl[128 * SK];
    __shared__ uint32_t sBh[128 * SK], sBl[128 * SK];
    __shared__ int rowidx[128];
    __shared__ float s_bias[128];
    __shared__ float red_s[4][128], red_q[4][128];

    const int t = threadIdx.x, tile = blockIdx.x;
    if (t < 128) { rowidx[t] = ei[tile * 128 + t]; s_bias[t] = bias[t]; }
    __syncthreads();

    const int warp = t >> 5, lane = t & 31, g = lane >> 2, t4 = lane & 3;
    const int wm = (warp >> 2) * 32, wn = (warp & 3) * 32;
    const int m = t >> 2, q = t & 3;
    const int n = t >> 2, qb = t & 3;

    const int rA = (lane & 7) + ((lane >> 3) & 1) * 8;
    const int cH = (lane >> 4) * 4;
    const uint32_t aH0 = smaddr(&sAh[(wm + rA) * SK + cH]);
    const uint32_t aH1 = smaddr(&sAh[(wm + 16 + rA) * SK + cH]);
    const uint32_t aL0 = smaddr(&sAl[(wm + rA) * SK + cH]);
    const uint32_t aL1 = smaddr(&sAl[(wm + 16 + rA) * SK + cH]);
    const int rB = lane & 15;
    const uint32_t bH0 = smaddr(&sBh[(wn + rB) * SK + cH]);
    const uint32_t bH1 = smaddr(&sBh[(wn + 16 + rB) * SK + cH]);
    const uint32_t bL0 = smaddr(&sBl[(wn + rB) * SK + cH]);
    const uint32_t bL1 = smaddr(&sBl[(wn + 16 + rB) * SK + cH]);

    float acc[2][4][4];
#pragma unroll
    for (int i = 0; i < 2; i++)
#pragma unroll
        for (int j = 0; j < 4; j++)
#pragma unroll
            for (int k = 0; k < 4; k++) acc[i][j][k] = 0.f;

    float4 va0, va1;
    uint4 qh, ql;
    {
        const float* src = x + (size_t)rowidx[m] * ND + q * 8;
        va0 = ((const float4*)src)[0]; va1 = ((const float4*)src)[1];
        qh = *(const uint4*)&g_W1T_hi[n * 64 + qb * 4];
        ql = *(const uint4*)&g_W1T_lo[n * 64 + qb * 4];
    }

#pragma unroll
    for (int s = 0; s < 4; s++) {
        {
            uint32_t h0, l0, h1, l1, h2, l2, h3, l3;
            split2(va0.x, va0.y, h0, l0); split2(va0.z, va0.w, h1, l1);
            split2(va1.x, va1.y, h2, l2); split2(va1.z, va1.w, h3, l3);
            *(uint4*)&sAh[m * SK + q * 4] = make_uint4(h0, h1, h2, h3);
            *(uint4*)&sAl[m * SK + q * 4] = make_uint4(l0, l1, l2, l3);
        }
        {
            *(uint4*)&sBh[n * SK + qb * 4] = qh;
            *(uint4*)&sBl[n * SK + qb * 4] = ql;
        }
        __syncthreads();
        if (s < 3) {
            int kb = (s + 1) * 32 + q * 8;
            const float* src = (s + 1 < 2)
                ? (x + (size_t)rowidx[m] * ND + kb)
                : (ea + (size_t)(tile * 128 + m) * ND + (kb - 64));
            va0 = ((const float4*)src)[0]; va1 = ((const float4*)src)[1];
            qh = *(const uint4*)&g_W1T_hi[n * 64 + (s + 1) * 16 + qb * 4];
            ql = *(const uint4*)&g_W1T_lo[n * 64 + (s + 1) * 16 + qb * 4];
        }
        mma_chunk_ldsm(aH0, aH1, aL0, aL1, bH0, bH1, bL0, bL1, acc);
        __syncthreads();
    }

    // epilogue: +bias, STG.128 h1 via lane-pair shuffle, column stats
    float s8[8] = {0, 0, 0, 0, 0, 0, 0, 0}, q8[8] = {0, 0, 0, 0, 0, 0, 0, 0};
    const int odd = t4 & 1;
#pragma unroll
    for (int mt = 0; mt < 2; mt++) {
        int r0 = wm + mt * 16 + g;
#pragma unroll
        for (int nt = 0; nt < 4; nt++) {
            int c = wn + nt * 8 + 2 * t4;
            float bx = s_bias[c], by = s_bias[c + 1];
            float v00 = acc[mt][nt][0] + bx, v01 = acc[mt][nt][1] + by;
            float v10 = acc[mt][nt][2] + bx, v11 = acc[mt][nt][3] + by;
            // stats on pre-shuffle values (identical to proven round-8 math)
            s8[nt * 2]     += v00 + v10;
            s8[nt * 2 + 1] += v01 + v11;
            q8[nt * 2]     += v00 * v00 + v10 * v10;
            q8[nt * 2 + 1] += v01 * v01 + v11 * v11;
            // lane-pair exchange: even lane keeps row r0, odd keeps row r0+8
            float e0 = odd ? v00 : v10;
            float e1 = odd ? v01 : v11;
            float p0 = __shfl_xor_sync(0xffffffffu, e0, 1);
            float p1 = __shfl_xor_sync(0xffffffffu, e1, 1);
            int row = r0 + odd * 8;
            int cb  = wn + nt * 8 + (t4 & 2) * 2;
            float4 quad = odd ? make_float4(p0, p1, v10, v11)
                              : make_float4(v00, v01, p0, p1);
            *(float4*)&g_h1[(size_t)(tile * 128 + row) * H + cb] = quad;
        }
    }
#pragma unroll
    for (int j = 0; j < 8; j++)
#pragma unroll
        for (int o = 4; o < 32; o <<= 1) {
            s8[j] += __shfl_xor_sync(0xffffffffu, s8[j], o);
            q8[j] += __shfl_xor_sync(0xffffffffu, q8[j], o);
        }
    if (lane < 4) {
        int wr = warp >> 2;
#pragma unroll
        for (int nt = 0; nt < 4; nt++) {
            red_s[wr][wn + nt * 8 + 2 * lane]     = s8[nt * 2];
            red_s[wr][wn + nt * 8 + 2 * lane + 1] = s8[nt * 2 + 1];
            red_q[wr][wn + nt * 8 + 2 * lane]     = q8[nt * 2];
            red_q[wr][wn + nt * 8 + 2 * lane + 1] = q8[nt * 2 + 1];
        }
    }
    __syncthreads();
    if (t < 128) {
        atomicAdd(&g_sum[t],   red_s[0][t] + red_s[1][t] + red_s[2][t] + red_s[3][t]);
        atomicAdd(&g_sumsq[t], red_q[0][t] + red_q[1][t] + red_q[2][t] + red_q[3][t]);
    }
}

// ============================================================================
// Edge GEMM2 + scatter: agg[col] += relu(BN(h1)) @ W2a + b2a
// Scatter via red.global.add.v4.f32 (4x fewer RED ops than scalar).
// ============================================================================
__global__ __launch_bounds__(512, 1) void edge_mma2(
    const int* __restrict__ ei, const float* __restrict__ bias) {
    __shared__ uint32_t sAh[128 * SK], sAl[128 * SK];
    __shared__ uint32_t sBh[128 * SK], sBl[128 * SK];
    __shared__ int colidx[128];
    __shared__ float s_bias[128], s_sc[128], s_sh[128];

    const int t = threadIdx.x, tile = blockIdx.x;
    if (t < 128) {
        colidx[t] = ei[NEDGES + tile * 128 + t];
        s_bias[t] = bias[t];
        s_sc[t] = g_scale[t];
        s_sh[t] = g_shift[t];
    }
    __syncthreads();

    const int warp = t >> 5, lane = t & 31, g = lane >> 2, t4 = lane & 3;
    const int wm = (warp >> 2) * 32, wn = (warp & 3) * 32;
    const int m = t >> 2, q = t & 3;
    const int n = t >> 2, qb = t & 3;

    const int rA = (lane & 7) + ((lane >> 3) & 1) * 8;
    const int cH = (lane >> 4) * 4;
    const uint32_t aH0 = smaddr(&sAh[(wm + rA) * SK + cH]);
    const uint32_t aH1 = smaddr(&sAh[(wm + 16 + rA) * SK + cH]);
    const uint32_t aL0 = smaddr(&sAl[(wm + rA) * SK + cH]);
    const uint32_t aL1 = smaddr(&sAl[(wm + 16 + rA) * SK + cH]);
    const int rB = lane & 15;
    const uint32_t bH0 = smaddr(&sBh[(wn + rB) * SK + cH]);
    const uint32_t bH1 = smaddr(&sBh[(wn + 16 + rB) * SK + cH]);
    const uint32_t bL0 = smaddr(&sBl[(wn + rB) * SK + cH]);
    const uint32_t bL1 = smaddr(&sBl[(wn + 16 + rB) * SK + cH]);

    float acc[2][4][4];
#pragma unroll
    for (int i = 0; i < 2; i++)
#pragma unroll
        for (int j = 0; j < 4; j++)
#pragma unroll
            for (int k = 0; k < 4; k++) acc[i][j][k] = 0.f;

    float4 va0, va1;
    uint4 qh, ql;
    {
        const float* src = g_h1 + (size_t)(tile * 128 + m) * H + q * 8;
        va0 = ((const float4*)src)[0]; va1 = ((const float4*)src)[1];
        qh = *(const uint4*)&g_W2T_hi[n * 64 + qb * 4];
        ql = *(const uint4*)&g_W2T_lo[n * 64 + qb * 4];
    }

#pragma unroll
    for (int s = 0; s < 4; s++) {
        {
            int kb = s * 32 + q * 8;
            float4 v0 = va0, v1 = va1;
            v0.x = fmaxf(fmaf(v0.x, s_sc[kb],     s_sh[kb]),     0.f);
            v0.y = fmaxf(fmaf(v0.y, s_sc[kb + 1], s_sh[kb + 1]), 0.f);
            v0.z = fmaxf(fmaf(v0.z, s_sc[kb + 2], s_sh[kb + 2]), 0.f);
            v0.w = fmaxf(fmaf(v0.w, s_sc[kb + 3], s_sh[kb + 3]), 0.f);
            v1.x = fmaxf(fmaf(v1.x, s_sc[kb + 4], s_sh[kb + 4]), 0.f);
            v1.y = fmaxf(fmaf(v1.y, s_sc[kb + 5], s_sh[kb + 5]), 0.f);
            v1.z = fmaxf(fmaf(v1.z, s_sc[kb + 6], s_sh[kb + 6]), 0.f);
            v1.w = fmaxf(fmaf(v1.w, s_sc[kb + 7], s_sh[kb + 7]), 0.f);
            uint32_t h0, l0, h1, l1, h2, l2, h3, l3;
            split2(v0.x, v0.y, h0, l0); split2(v0.z, v0.w, h1, l1);
            split2(v1.x, v1.y, h2, l2); split2(v1.z, v1.w, h3, l3);
            *(uint4*)&sAh[m * SK + q * 4] = make_uint4(h0, h1, h2, h3);
            *(uint4*)&sAl[m * SK + q * 4] = make_uint4(l0, l1, l2, l3);
        }
        {
            *(uint4*)&sBh[n * SK + qb * 4] = qh;
            *(uint4*)&sBl[n * SK + qb * 4] = ql;
        }
        __syncthreads();
        if (s < 3) {
            const float* src = g_h1 + (size_t)(tile * 128 + m) * H + (s + 1) * 32 + q * 8;
            va0 = ((const float4*)src)[0]; va1 = ((const float4*)src)[1];
            qh = *(const uint4*)&g_W2T_hi[n * 64 + (s + 1) * 16 + qb * 4];
            ql = *(const uint4*)&g_W2T_lo[n * 64 + (s + 1) * 16 + qb * 4];
        }
        mma_chunk_ldsm(aH0, aH1, aL0, aL1, bH0, bH1, bL0, bL1, acc);
        __syncthreads();
    }

    // epilogue: + bias, lane-pair shuffle, v4 reduction scatter
    const int odd = t4 & 1;
#pragma unroll
    for (int mt = 0; mt < 2; mt++) {
        int r0 = wm + mt * 16 + g;
#pragma unroll
        for (int nt = 0; nt < 4; nt++) {
            int c = wn + nt * 8 + 2 * t4;
            float bx = s_bias[c], by = s_bias[c + 1];
            float v00 = acc[mt][nt][0] + bx, v01 = acc[mt][nt][1] + by;
            float v10 = acc[mt][nt][2] + bx, v11 = acc[mt][nt][3] + by;
            float e0 = odd ? v00 : v10;
            float e1 = odd ? v01 : v11;
            float p0 = __shfl_xor_sync(0xffffffffu, e0, 1);
            float p1 = __shfl_xor_sync(0xffffffffu, e1, 1);
            int row = r0 + odd * 8;
            int node = colidx[row];
            int cb  = wn + nt * 8 + (t4 & 2) * 2;
            if (odd)
                red_add_v4(&g_agg[(size_t)node * H + cb], p0, p1, v10, v11);
            else
                red_add_v4(&g_agg[(size_t)node * H + cb], v00, v01, p0, p1);
        }
    }
}

// ---------------- f32x2 helpers (node-side SIMT kernels, proven) -------------
__device__ __forceinline__ unsigned long long pack2(float a, float b) {
    unsigned long long r; asm("mov.b64 %0, {%1, %2};" : "=l"(r) : "f"(a), "f"(b)); return r;
}
__device__ __forceinline__ void fma2(unsigned long long& d, unsigned long long a,
                                     unsigned long long b) {
    asm("fma.rn.f32x2 %0, %1, %2, %0;" : "+l"(d) : "l"(a), "l"(b));
}
__device__ __forceinline__ float2 unpack2(unsigned long long v) {
    float2 f; asm("mov.b64 {%0, %1}, %2;" : "=f"(f.x), "=f"(f.y) : "l"(v)); return f;
}

// ============================================================================
// Node GEMM1 (SIMT, proven): h2 = concat(x, agg) @ W1b + b1b + stats
// ============================================================================
__global__ __launch_bounds__(256) void node_gemm1(
    const float* __restrict__ x, const float* __restrict__ W,
    const float* __restrict__ bias) {
    __shared__ float As[16][64];
    __shared__ float Ws[16][128];
    __shared__ float red[16][128];

    const int tid = threadIdx.x;
    const int tx = tid & 15, ty = tid >> 4;
    const int row0 = blockIdx.x * 64;

    unsigned long long acc[4][4];
#pragma unroll
    for (int i = 0; i < 4; i++)
#pragma unroll
        for (int j = 0; j < 4; j++) acc[i][j] = 0ULL;

    const int lr = tid & 63;
    const int lk4 = (tid >> 6) << 2;
    const int n_load = row0 + lr;

    for (int k0 = 0; k0 < 192; k0 += 16) {
        int kk = k0 + lk4;
        float4 v = {0.f, 0.f, 0.f, 0.f};
        if (n_load < NNODES) {
            if (kk < 64) v = *(const float4*)&x[(size_t)n_load * ND + kk];
            else         v = *(const float4*)&g_agg[(size_t)n_load * H + (kk - 64)];
        }
        As[lk4 + 0][lr] = v.x; As[lk4 + 1][lr] = v.y;
        As[lk4 + 2][lr] = v.z; As[lk4 + 3][lr] = v.w;

        int idx = tid * 8, wkr = idx >> 7, wc = idx & 127;
        *(float4*)&Ws[wkr][wc]     = *(const float4*)&W[(k0 + wkr) * H + wc];
        *(float4*)&Ws[wkr][wc + 4] = *(const float4*)&W[(k0 + wkr) * H + wc + 4];
        __syncthreads();

#pragma unroll
        for (int k = 0; k < 16; k++) {
            float4 a4 = *(const float4*)&As[k][ty * 4];
            float4 b0 = *(const float4*)&Ws[k][tx * 8];
            float4 b1 = *(const float4*)&Ws[k][tx * 8 + 4];
            unsigned long long bp[4] = {pack2(b0.x, b0.y), pack2(b0.z, b0.w),
                                        pack2(b1.x, b1.y), pack2(b1.z, b1.w)};
            float ar[4] = {a4.x, a4.y, a4.z, a4.w};
#pragma unroll
            for (int i = 0; i < 4; i++) {
                unsigned long long ap = pack2(ar[i], ar[i]);
#pragma unroll
                for (int j = 0; j < 4; j++) fma2(acc[i][j], ap, bp[j]);
            }
        }
        __syncthreads();
    }

    float2 s2[4], q2[4];
#pragma unroll
    for (int j = 0; j < 4; j++) { s2[j] = make_float2(0.f, 0.f); q2[j] = make_float2(0.f, 0.f); }
#pragma unroll
    for (int i = 0; i < 4; i++) {
        int nn = row0 + ty * 4 + i;
        if (nn >= NNODES) continue;
#pragma unroll
        for (int j = 0; j < 4; j++) {
            int c0 = tx * 8 + 2 * j;
            float2 v = unpack2(acc[i][j]);
            v.x += bias[c0]; v.y += bias[c0 + 1];
            *(float2*)&g_h2[(size_t)nn * H + c0] = v;
            s2[j].x += v.x; s2[j].y += v.y;
            q2[j].x += v.x * v.x; q2[j].y += v.y * v.y;
        }
    }
#pragma unroll
    for (int j = 0; j < 4; j++) *(float2*)&red[ty][tx * 8 + 2 * j] = s2[j];
    __syncthreads();
    if (tid < 128) {
        float s = 0.f;
#pragma unroll
        for (int tt = 0; tt < 16; tt++) s += red[tt][tid];
        atomicAdd(&g_sum[tid], s);
    }
    __syncthreads();
#pragma unroll
    for (int j = 0; j < 4; j++) *(float2*)&red[ty][tx * 8 + 2 * j] = q2[j];
    __syncthreads();
    if (tid < 128) {
        float s = 0.f;
#pragma unroll
        for (int tt = 0; tt < 16; tt++) s += red[tt][tid];
        atomicAdd(&g_sumsq[tid], s);
    }
}

// ============================================================================
// Node GEMM2 (SIMT, proven): out = relu(BN(h2)) @ W2b + b2b
// ============================================================================
__global__ __launch_bounds__(256) void node_gemm2(
    const float* __restrict__ W, const float* __restrict__ bias,
    float* __restrict__ out) {
    __shared__ float As[16][64];
    __shared__ float Ws[16][64];

    const int tid = threadIdx.x;
    const int tx = tid & 15, ty = tid >> 4;
    const int row0 = blockIdx.x * 64;

    unsigned long long acc[4][2];
#pragma unroll
    for (int i = 0; i < 4; i++) { acc[i][0] = 0ULL; acc[i][1] = 0ULL; }

    const int lr = tid & 63;
    const int lk4 = (tid >> 6) << 2;
    const int n_load = row0 + lr;

    for (int k0 = 0; k0 < 128; k0 += 16) {
        int kk = k0 + lk4;
        float4 v = {0.f, 0.f, 0.f, 0.f};
        if (n_load < NNODES) {
            v = *(const float4*)&g_h2[(size_t)n_load * H + kk];
            float4 sc = *(const float4*)&g_scale[kk];
            float4 sh = *(const float4*)&g_shift[kk];
            v.x = fmaxf(fmaf(v.x, sc.x, sh.x), 0.f);
            v.y = fmaxf(fmaf(v.y, sc.y, sh.y), 0.f);
            v.z = fmaxf(fmaf(v.z, sc.z, sh.z), 0.f);
            v.w = fmaxf(fmaf(v.w, sc.w, sh.w), 0.f);
        }
        As[lk4 + 0][lr] = v.x; As[lk4 + 1][lr] = v.y;
        As[lk4 + 2][lr] = v.z; As[lk4 + 3][lr] = v.w;

        int idx = tid * 4, wkr = idx >> 6, wc = idx & 63;
        *(float4*)&Ws[wkr][wc] = *(const float4*)&W[(k0 + wkr) * OUTD + wc];
        __syncthreads();

#pragma unroll
        for (int k = 0; k < 16; k++) {
            float4 a4 = *(const float4*)&As[k][ty * 4];
            float4 b0 = *(const float4*)&Ws[k][tx * 4];
            unsigned long long bp[2] = {pack2(b0.x, b0.y), pack2(b0.z, b0.w)};
            float ar[4] = {a4.x, a4.y, a4.z, a4.w};
#pragma unroll
            for (int i = 0; i < 4; i++) {
                unsigned long long ap = pack2(ar[i], ar[i]);
                fma2(acc[i][0], ap, bp[0]);
                fma2(acc[i][1], ap, bp[1]);
            }
        }
        __syncthreads();
    }

#pragma unroll
    for (int i = 0; i < 4; i++) {
        int nn = row0 + ty * 4 + i;
        if (nn >= NNODES) continue;
#pragma unroll
        for (int j = 0; j < 2; j++) {
            int c0 = tx * 4 + 2 * j;
            float2 v = unpack2(acc[i][j]);
            v.x += bias[c0]; v.y += bias[c0 + 1];
            *(float2*)&out[(size_t)nn * OUTD + c0] = v;
        }
    }
}

// ============================================================================
extern "C" void kernel_launch(void* const* d_in, const int* in_sizes, int n_in,
                              void* d_out, int out_size) {
    const float* x    = (const float*)d_in[0];
    const int*   ei   = (const int*)d_in[1];
    const float* ea   = (const float*)d_in[2];
    const float* W1a  = (const float*)d_in[5];
    const float* b1a  = (const float*)d_in[6];
    const float* g1a  = (const float*)d_in[7];
    const float* be1a = (const float*)d_in[8];
    const float* W2a  = (const float*)d_in[9];
    const float* b2a  = (const float*)d_in[10];
    const float* W1b  = (const float*)d_in[11];
    const float* b1b  = (const float*)d_in[12];
    const float* g1b  = (const float*)d_in[13];
    const float* be1b = (const float*)d_in[14];
    const float* W2b  = (const float*)d_in[15];
    const float* b2b  = (const float*)d_in[16];
    float* out = (float*)d_out;

    const int node_blocks = (NNODES + 63) / 64;  // 782

    zero_kernel<<<(NNODES * H / 4 + 255) / 256, 256>>>();
    wsplit<<<32, 256>>>(W1a, 0);
    wsplit<<<32, 256>>>(W2a, 1);

    edge_mma1<<<NTILES2, 512>>>(x, ei, ea, b1a);
    finalize_bn<<<1, 128>>>(g1a, be1a, 1.0f / (float)NEDGES);
    edge_mma2<<<NTILES2, 512>>>(ei, b2a);
    node_gemm1<<<node_blocks, 256>>>(x, W1b, b1b);
    finalize_bn<<<1, 128>>>(g1b, be1b, 1.0f / (float)NNODES);
    node_gemm2<<<node_blocks, 256>>>(W2b, b2b, out);
}